// round 14
// baseline (speedup 1.0000x reference)
#include <cuda_runtime.h>
#include <cuda_fp16.h>
#include <math.h>
#include <stdint.h>

#define BATCH   2
#define S0      4095
#define SEQ     4096
#define DMODEL  512
#define NH      8
#define DH      64
#define DFF     2048
#define MROWS   (BATCH * S0)    // 8190
#define MPAD    (BATCH * SEQ)   // 8192
#define QKVN    1536
#define QKVW    768             // words per qkv row

// ---------------- scratch ----------------
__device__ __align__(16) uint32_t g_xh[(size_t)MPAD * DMODEL / 2];
__device__ __align__(16) uint32_t g_Wqkv[(size_t)QKVN * DMODEL / 2];
__device__ __align__(16) uint32_t g_W1t[(size_t)DFF * DMODEL / 2];
__device__ __align__(16) uint32_t g_W2t[(size_t)DMODEL * DFF / 2];
__device__ __align__(16) float    g_bqkv[QKVN];
__device__ __align__(16) uint32_t g_qkvh[(size_t)MPAD * QKVW];   // packed fp16
__device__ __align__(16) float    g_attn[(size_t)MPAD * DMODEL];
__device__ __align__(16) float    g_hn[(size_t)MROWS * DMODEL];
__device__ __align__(16) uint32_t g_hnh[(size_t)MROWS * DMODEL / 2];
__device__ __align__(16) uint32_t g_acth[(size_t)MROWS * DFF / 2];

__device__ __forceinline__ uint32_t smem_u32(const void* p) {
    uint32_t a;
    asm("{ .reg .u64 t; cvta.to.shared.u64 t, %1; cvt.u32.u64 %0, t; }"
        : "=r"(a) : "l"(p));
    return a;
}
__device__ __forceinline__ uint32_t f2h2(float a, float b) {
    __half2 h = __floats2half2_rn(a, b);
    return *(uint32_t*)&h;
}
__device__ __forceinline__ float2 h22f2(uint32_t w) {
    __half2 h = *(__half2*)&w;
    return __half22float2(h);
}
__device__ __forceinline__ float gelu_exact(float v) {
    return 0.5f * v * (1.0f + erff(v * 0.70710678118654752440f));
}
__device__ __forceinline__ void mma_f16(float* c, const uint32_t* a,
                                        const uint32_t* b) {
    asm volatile(
        "mma.sync.aligned.m16n8k16.row.col.f32.f16.f16.f32 "
        "{%0,%1,%2,%3}, {%4,%5,%6,%7}, {%8,%9}, {%0,%1,%2,%3};"
        : "+f"(c[0]), "+f"(c[1]), "+f"(c[2]), "+f"(c[3])
        : "r"(a[0]), "r"(a[1]), "r"(a[2]), "r"(a[3]), "r"(b[0]), "r"(b[1]));
}
#define LDSM4(r0, r1, r2, r3, addr) \
    asm volatile("ldmatrix.sync.aligned.m8n8.x4.shared.b16 {%0,%1,%2,%3}, [%4];" \
        : "=r"(r0), "=r"(r1), "=r"(r2), "=r"(r3) : "r"(addr))

__device__ __forceinline__ void cpa16(uint32_t dst, const void* src, bool v) {
    int sz = v ? 16 : 0;
    asm volatile("cp.async.cg.shared.global [%0], [%1], 16, %2;"
        :: "r"(dst), "l"(src), "r"(sz) : "memory");
}

// ---------------------------------------------------------------------------
// fp16 GEMM: C[M,N] = A[M,K] @ B[N,K]^T.  Block BMx128 (BM=128 or 64),
// 8 warps (2m x 4n), warp tile (BM/2)x32, BK=32, 4-stage cp.async,
// stride-20-word SMEM, ldmatrix.
// BM=128: 2 CTAs/SM (126 regs). BM=64: 3 CTAs/SM (<=84 regs, 60KB smem).
// GEMM B addressing: lane bit3 -> k-offset, bit4 -> row+8, so B-frag pairs
// are {r0,r1} (rows0-7) and {r2,r3} (rows8-15)  [NOT the attn pairing].
// MODE 0: fp16x2 = acc + bias     MODE 1: fp16x2 = gelu(acc + bias)
// MODE 2: fp32   = acc + bias + res
// ---------------------------------------------------------------------------
#define GSTAGES 4

template<int MODE, int BM>
__global__ __launch_bounds__(256, (BM == 64) ? 3 : 2)
void hgemm2(const uint32_t* __restrict__ A, const uint32_t* __restrict__ B,
            const float* __restrict__ bias, const float* __restrict__ res,
            float* __restrict__ outf, uint32_t* __restrict__ outh,
            int M, int N, int K)
{
    constexpr int MF   = BM / 32;            // m-frags per warp (4 or 2)
    constexpr int AW_W = BM * 20;            // A words per stage
    constexpr int STGW = AW_W + 2560;        // + B 128x20
    constexpr int NCH  = (BM * 4 + 512) / 256;  // load iterations

    extern __shared__ __align__(16) uint32_t S[];
    const uint32_t sm0 = smem_u32(S);
    const int tid  = threadIdx.x;
    const int lane = tid & 31;
    const int wid  = tid >> 5;
    const int wm   = wid & 1;       // 2 warp-rows x (BM/2)
    const int wn   = wid >> 1;      // 4 warp-cols x 32
    const int bn   = blockIdx.x;
    const int bm   = blockIdx.y;
    const int K2   = K >> 1;
    const int NT   = K >> 5;

    const int aRow = wm * (BM / 2) + (lane & 15);
    const int aW   = (lane >> 4) << 2;
    const int bRow = wn * 32 + (lane & 7) + ((lane >> 4) << 3);
    const int bW   = ((lane >> 3) & 1) << 2;

    auto load_stage = [&](int kt, int st) {
        const uint32_t base = sm0 + st * (STGW * 4);
#pragma unroll
        for (int i = 0; i < NCH; i++) {
            int c = i * 256 + tid;              // 16B chunks: A = BM*4, B = 512
            bool isA = (c < BM * 4);
            int idx  = isA ? c : c - BM * 4;
            int row  = idx >> 2, w = idx & 3;
            int grow = isA ? (bm * BM + row) : (bn * 128 + row);
            bool valid = (!isA) || (grow < M);
            const uint32_t* src = (isA ? A : B)
                + (size_t)(valid ? grow : 0) * K2 + kt * 16 + w * 4;
            uint32_t dst = base + ((isA ? 0 : AW_W) + row * 20 + w * 4) * 4;
            cpa16(dst, src, valid);
        }
        asm volatile("cp.async.commit_group;" ::: "memory");
    };

    float acc[MF][4][4];
#pragma unroll
    for (int i = 0; i < MF; i++)
#pragma unroll
        for (int j = 0; j < 4; j++)
#pragma unroll
            for (int q = 0; q < 4; q++) acc[i][j][q] = 0.0f;

    load_stage(0, 0);
    if (NT > 1) load_stage(1, 1);
    if (NT > 2) load_stage(2, 2);

    for (int kt = 0; kt < NT; kt++) {
        if (kt + 2 < NT)      asm volatile("cp.async.wait_group 2;" ::: "memory");
        else if (kt + 1 < NT) asm volatile("cp.async.wait_group 1;" ::: "memory");
        else                  asm volatile("cp.async.wait_group 0;" ::: "memory");
        __syncthreads();
        if (kt + 3 < NT) load_stage(kt + 3, (kt + 3) % GSTAGES);

        const uint32_t sA = sm0 + (kt % GSTAGES) * (STGW * 4);
        const uint32_t sB = sA + AW_W * 4;
#pragma unroll
        for (int kh = 0; kh < 2; kh++) {
            uint32_t a[MF][4], b[4][2];
#pragma unroll
            for (int mf = 0; mf < MF; mf++) {
                uint32_t ad = sA + (((aRow + mf * 16) * 20) + aW + kh * 8) * 4;
                LDSM4(a[mf][0], a[mf][1], a[mf][2], a[mf][3], ad);
            }
#pragma unroll
            for (int bp = 0; bp < 2; bp++) {
                uint32_t ad = sB + (((bRow + bp * 16) * 20) + bW + kh * 8) * 4;
                LDSM4(b[2 * bp][0], b[2 * bp][1],
                      b[2 * bp + 1][0], b[2 * bp + 1][1], ad);
            }
#pragma unroll
            for (int mf = 0; mf < MF; mf++)
#pragma unroll
                for (int nf = 0; nf < 4; nf++)
                    mma_f16(acc[mf][nf], a[mf], b[nf]);
        }
    }

#pragma unroll
    for (int mf = 0; mf < MF; mf++) {
#pragma unroll
        for (int nf = 0; nf < 4; nf++) {
            const int r0  = bm * BM + wm * (BM / 2) + mf * 16 + (lane >> 2);
            const int col = bn * 128 + wn * 32 + nf * 8 + (lane & 3) * 2;
            const float b0 = bias[col], b1 = bias[col + 1];
#pragma unroll
            for (int half = 0; half < 2; half++) {
                const int r = r0 + half * 8;
                if (r >= M) continue;
                float v0 = acc[mf][nf][half * 2 + 0] + b0;
                float v1 = acc[mf][nf][half * 2 + 1] + b1;
                if (MODE == 0) {
                    outh[(size_t)r * (N >> 1) + (col >> 1)] = f2h2(v0, v1);
                } else if (MODE == 1) {
                    outh[(size_t)r * (N >> 1) + (col >> 1)] =
                        f2h2(gelu_exact(v0), gelu_exact(v1));
                } else {
                    const float* rr = res + (size_t)r * N + col;
                    *(float2*)&outf[(size_t)r * N + col] =
                        make_float2(v0 + rr[0], v1 + rr[1]);
                }
            }
        }
    }
}

#define GSMEM_128 (GSTAGES * (128 * 20 + 2560) * 4)   // 81920
#define GSMEM_64  (GSTAGES * (64 * 20 + 2560) * 4)    // 61440

// ---------------------------------------------------------------------------
// prep kernels (coalesced transposes via SMEM tiles)
// ---------------------------------------------------------------------------
__global__ void prep_x(const float* __restrict__ x, uint32_t* __restrict__ o)
{
    size_t idx = (size_t)blockIdx.x * blockDim.x + threadIdx.x;
    if (idx >= (size_t)MPAD * DMODEL / 2) return;
    int r = (int)(idx >> 8), w = (int)(idx & 255);
    int s = r & (SEQ - 1), b = r >> 12;
    float v0 = 0.f, v1 = 0.f;
    if (s < S0) {
        const float* p = x + ((size_t)b * S0 + s) * DMODEL + 2 * w;
        v0 = p[0]; v1 = p[1];
    }
    o[idx] = f2h2(v0, v1);
}

__device__ __forceinline__ void wt_tile(const float* __restrict__ W,
                                        uint32_t* __restrict__ o,
                                        int N, int dstStride, int dstRowOff,
                                        float scale, int k0, int n0)
{
    __shared__ float ts[64][33];
    const int tid = threadIdx.x;
#pragma unroll
    for (int i = 0; i < 8; i++) {
        int t = i * 256 + tid;
        int kr = t >> 5, nc = t & 31;
        ts[kr][nc] = W[(size_t)(k0 + kr) * N + n0 + nc];
    }
    __syncthreads();
#pragma unroll
    for (int i = 0; i < 4; i++) {
        int t = i * 256 + tid;
        int n = t >> 5, w = t & 31;
        o[(size_t)(dstRowOff + n0 + n) * dstStride + (k0 >> 1) + w] =
            f2h2(ts[2 * w][n] * scale, ts[2 * w + 1][n] * scale);
    }
}

__global__ __launch_bounds__(256)
void prep_wqkv_t(const float* __restrict__ Wq, const float* __restrict__ Wk,
                 const float* __restrict__ Wv, uint32_t* __restrict__ o)
{
    const int z = blockIdx.z;
    const float* W = (z == 0) ? Wq : (z == 1) ? Wk : Wv;
    float sc = (z == 0) ? 0.125f : 1.0f;
    wt_tile(W, o, DMODEL, 256, z * 512, sc, blockIdx.x * 64, blockIdx.y * 32);
}

__global__ __launch_bounds__(256)
void prep_wt2(const float* __restrict__ W, uint32_t* __restrict__ o,
              int N, int dstStride)
{
    wt_tile(W, o, N, dstStride, 0, 1.0f, blockIdx.x * 64, blockIdx.y * 32);
}

__global__ void prep_bias(const float* __restrict__ bq, const float* __restrict__ bk,
                          const float* __restrict__ bv, float* __restrict__ o)
{
    int n = blockIdx.x * blockDim.x + threadIdx.x;
    if (n >= QKVN) return;
    o[n] = (n < 512) ? bq[n] * 0.125f
         : (n < 1024) ? bk[n - 512] : bv[n - 1024];
}

// ---------------------------------------------------------------------------
// Tensor-core sliding-window attention (unchanged — proven; its ldmatrix
// addressing differs from the GEMM, so its B pairing {r0,r2} is correct).
// ---------------------------------------------------------------------------
#define AQ0 0
#define AK0 (64 * 72)
#define AV0 (AK0 + 320 * 72)
#define ASMEMH (AV0 + 64 * 328)
#define ASMEM (ASMEMH * 2)

__global__ __launch_bounds__(128, 1)
void attn_mma(const uint32_t* __restrict__ qkvh, float* __restrict__ out)
{
    extern __shared__ __align__(16) unsigned short SH[];
    const uint32_t sb = smem_u32(SH);
    const int tid  = threadIdx.x;
    const int lane = tid & 31;
    const int w    = tid >> 5;
    const int h    = blockIdx.y;
    const int b    = blockIdx.z;
    const int t0   = blockIdx.x * 64;
    const size_t rowbase = (size_t)b * SEQ;

#pragma unroll
    for (int i = 0; i < 4; i++) {
        int c = i * 128 + tid;
        int row = c >> 3, c16 = c & 7;
        const uint32_t* src = qkvh + (rowbase + t0 + row) * QKVW + h * 32 + c16 * 4;
        *(uint4*)&SH[AQ0 + row * 72 + c16 * 8] = *(const uint4*)src;
    }
#pragma unroll
    for (int i = 0; i < 20; i++) {
        int c = i * 128 + tid;
        int row = c >> 3, c16 = c & 7;
        int key = t0 - 128 + row;
        key = key < 0 ? 0 : (key > SEQ - 1 ? SEQ - 1 : key);
        const uint32_t* src = qkvh + (rowbase + key) * QKVW + 256 + h * 32 + c16 * 4;
        *(uint4*)&SH[AK0 + row * 72 + c16 * 8] = *(const uint4*)src;
    }
#pragma unroll
    for (int i = 0; i < 20; i++) {
        int c = i * 128 + tid;
        int row = c >> 3, c16 = c & 7;
        int key = t0 - 128 + row;
        key = key < 0 ? 0 : (key > SEQ - 1 ? SEQ - 1 : key);
        const uint32_t* src = qkvh + (rowbase + key) * QKVW + 512 + h * 32 + c16 * 4;
        uint4 v = *(const uint4*)src;
        const unsigned short* hv = (const unsigned short*)&v;
#pragma unroll
        for (int j = 0; j < 8; j++)
            SH[AV0 + (c16 * 8 + j) * 328 + row] = hv[j];
    }
    __syncthreads();

    const int l15 = lane & 15;
    const int lh8 = (lane >> 4) << 3;
    const int kl0 = (lane & 3) << 1;
    const int r   = 16 * w + (lane >> 2);

    uint32_t aq[4][4];
#pragma unroll
    for (int j = 0; j < 4; j++) {
        uint32_t ad = sb + ((16 * w + l15) * 72 + 16 * j + lh8) * 2;
        LDSM4(aq[j][0], aq[j][1], aq[j][2], aq[j][3], ad);
    }

    float od[8][4];
#pragma unroll
    for (int nf = 0; nf < 8; nf++)
#pragma unroll
        for (int q = 0; q < 4; q++) od[nf][q] = 0.0f;
    float m0 = -1e30f, m1 = -1e30f, l0 = 0.f, l1 = 0.f;

    for (int c = 0; c < 5; c++) {
        const int ks = t0 - 128 + 64 * c;
        if (ks + 63 < 0 || ks > S0 - 1) continue;

        float sc[8][4];
#pragma unroll
        for (int nf = 0; nf < 8; nf++)
#pragma unroll
            for (int q = 0; q < 4; q++) sc[nf][q] = 0.0f;

#pragma unroll
        for (int j = 0; j < 4; j++)
#pragma unroll
            for (int p = 0; p < 4; p++) {
                uint32_t r0, r1, r2, r3;
                uint32_t ad = sb + (AK0 + (c * 64 + 16 * p + l15) * 72
                                    + 16 * j + lh8) * 2;
                LDSM4(r0, r1, r2, r3, ad);
                uint32_t b0[2] = {r0, r2}, b1[2] = {r1, r3};
                mma_f16(sc[2 * p],     aq[j], b0);
                mma_f16(sc[2 * p + 1], aq[j], b1);
            }

        float mx0 = -1e30f, mx1 = -1e30f;
#pragma unroll
        for (int nf = 0; nf < 8; nf++) {
            int kl = 8 * nf + kl0;
            int u  = 64 * c + kl - r;
            int sg = ks + kl;
            bool k0ok = (sg >= 0) && (sg < S0);
            bool k1ok = (sg + 1 >= 0) && (sg + 1 < S0);
            bool v0 = k0ok && (u >= 0)     && (u <= 256);
            bool v1 = k1ok && (u + 1 >= 0) && (u + 1 <= 256);
            bool v2 = k0ok && (u - 8 >= 0) && (u - 8 <= 256);
            bool v3 = k1ok && (u - 7 >= 0) && (u - 7 <= 256);
            sc[nf][0] = v0 ? sc[nf][0] : -1e30f;
            sc[nf][1] = v1 ? sc[nf][1] : -1e30f;
            sc[nf][2] = v2 ? sc[nf][2] : -1e30f;
            sc[nf][3] = v3 ? sc[nf][3] : -1e30f;
            mx0 = fmaxf(mx0, fmaxf(sc[nf][0], sc[nf][1]));
            mx1 = fmaxf(mx1, fmaxf(sc[nf][2], sc[nf][3]));
        }
        mx0 = fmaxf(mx0, __shfl_xor_sync(0xffffffffu, mx0, 1));
        mx0 = fmaxf(mx0, __shfl_xor_sync(0xffffffffu, mx0, 2));
        mx1 = fmaxf(mx1, __shfl_xor_sync(0xffffffffu, mx1, 1));
        mx1 = fmaxf(mx1, __shfl_xor_sync(0xffffffffu, mx1, 2));

        float mn0 = fmaxf(m0, mx0), mn1 = fmaxf(m1, mx1);
        float s0 = __expf(m0 - mn0), s1 = __expf(m1 - mn1);
        float ls0 = 0.f, ls1 = 0.f;
        uint32_t pa[4][4];
#pragma unroll
        for (int nf = 0; nf < 8; nf++) {
            float e0 = __expf(sc[nf][0] - mn0);
            float e1 = __expf(sc[nf][1] - mn0);
            float e2 = __expf(sc[nf][2] - mn1);
            float e3 = __expf(sc[nf][3] - mn1);
            ls0 += e0 + e1; ls1 += e2 + e3;
            int j = nf >> 1, q = nf & 1;
            pa[j][2 * q]     = f2h2(e0, e1);
            pa[j][2 * q + 1] = f2h2(e2, e3);
        }
        ls0 += __shfl_xor_sync(0xffffffffu, ls0, 1);
        ls0 += __shfl_xor_sync(0xffffffffu, ls0, 2);
        ls1 += __shfl_xor_sync(0xffffffffu, ls1, 1);
        ls1 += __shfl_xor_sync(0xffffffffu, ls1, 2);
        l0 = l0 * s0 + ls0;
        l1 = l1 * s1 + ls1;
        m0 = mn0; m1 = mn1;
#pragma unroll
        for (int nf = 0; nf < 8; nf++) {
            od[nf][0] *= s0; od[nf][1] *= s0;
            od[nf][2] *= s1; od[nf][3] *= s1;
        }

#pragma unroll
        for (int j = 0; j < 4; j++)
#pragma unroll
            for (int p = 0; p < 4; p++) {
                uint32_t r0, r1, r2, r3;
                uint32_t ad = sb + (AV0 + (16 * p + l15) * 328
                                    + c * 64 + 16 * j + lh8) * 2;
                LDSM4(r0, r1, r2, r3, ad);
                uint32_t b0[2] = {r0, r2}, b1[2] = {r1, r3};
                mma_f16(od[2 * p],     pa[j], b0);
                mma_f16(od[2 * p + 1], pa[j], b1);
            }
    }

    {
        const uint32_t* kg = qkvh + (rowbase + SEQ - 1) * QKVW + 256 + h * 32
                           + (lane & 3) * 8;
        const uint32_t* q0 = (const uint32_t*)(SH + (size_t)(AQ0 + r * 72))
                           + (lane & 3) * 8;
        const uint32_t* q1 = (const uint32_t*)(SH + (size_t)(AQ0 + (r + 8) * 72))
                           + (lane & 3) * 8;
        float gs0 = 0.f, gs1 = 0.f;
#pragma unroll
        for (int i = 0; i < 8; i++) {
            float2 fk = h22f2(kg[i]);
            float2 f0 = h22f2(q0[i]);
            float2 f1 = h22f2(q1[i]);
            gs0 += f0.x * fk.x + f0.y * fk.y;
            gs1 += f1.x * fk.x + f1.y * fk.y;
        }
        gs0 += __shfl_xor_sync(0xffffffffu, gs0, 1);
        gs0 += __shfl_xor_sync(0xffffffffu, gs0, 2);
        gs1 += __shfl_xor_sync(0xffffffffu, gs1, 1);
        gs1 += __shfl_xor_sync(0xffffffffu, gs1, 2);

        float mn0 = fmaxf(m0, gs0), mn1 = fmaxf(m1, gs1);
        float s0 = __expf(m0 - mn0), s1 = __expf(m1 - mn1);
        float pg0 = __expf(gs0 - mn0), pg1 = __expf(gs1 - mn1);
        l0 = l0 * s0 + pg0;
        l1 = l1 * s1 + pg1;
        const uint32_t* vg = qkvh + (rowbase + SEQ - 1) * QKVW + 512 + h * 32
                           + (lane & 3);
#pragma unroll
        for (int nf = 0; nf < 8; nf++) {
            float2 fv = h22f2(vg[nf * 4]);
            od[nf][0] = od[nf][0] * s0 + pg0 * fv.x;
            od[nf][1] = od[nf][1] * s0 + pg0 * fv.y;
            od[nf][2] = od[nf][2] * s1 + pg1 * fv.x;
            od[nf][3] = od[nf][3] * s1 + pg1 * fv.y;
        }
    }

    const float inv0 = 1.0f / l0, inv1 = 1.0f / l1;
    const int t = t0 + r;
    float* o0 = out + ((size_t)b * SEQ + t) * DMODEL + h * DH + kl0;
    float* o1 = o0 + 8 * (size_t)DMODEL;
#pragma unroll
    for (int nf = 0; nf < 8; nf++) {
        *(float2*)(o0 + nf * 8) = make_float2(od[nf][0] * inv0, od[nf][1] * inv0);
        *(float2*)(o1 + nf * 8) = make_float2(od[nf][2] * inv1, od[nf][3] * inv1);
    }
}

// ---------------------------------------------------------------------------
// Residual + LayerNorm -> hn fp32 + packed fp16
// ---------------------------------------------------------------------------
__global__ __launch_bounds__(256)
void ln_kernel(const float* __restrict__ x, const float* __restrict__ attn,
               const float* __restrict__ gamma, const float* __restrict__ beta,
               float* __restrict__ hn, uint32_t* __restrict__ hnh)
{
    const int r = blockIdx.x;
    const int b = r / S0;
    const int s = r - b * S0;
    const int tid = threadIdx.x;
    const int c = tid * 2;

    float2 xv = *(const float2*)(x + (size_t)r * DMODEL + c);
    float2 av = *(const float2*)(attn + ((size_t)b * SEQ + s) * DMODEL + c);
    float h0 = xv.x + av.x;
    float h1 = xv.y + av.y;
    float sum = h0 + h1;
    float sq  = h0 * h0 + h1 * h1;
#pragma unroll
    for (int off = 16; off; off >>= 1) {
        sum += __shfl_xor_sync(0xffffffffu, sum, off);
        sq  += __shfl_xor_sync(0xffffffffu, sq,  off);
    }
    __shared__ float rs[8], rq[8];
    int w = tid >> 5, lane = tid & 31;
    if (lane == 0) { rs[w] = sum; rq[w] = sq; }
    __syncthreads();
    float ts = 0.f, tq = 0.f;
#pragma unroll
    for (int i = 0; i < 8; i++) { ts += rs[i]; tq += rq[i]; }
    float mu   = ts * (1.0f / DMODEL);
    float var  = tq * (1.0f / DMODEL) - mu * mu;
    float rstd = rsqrtf(var + 1e-5f);
    float v0 = (h0 - mu) * rstd * gamma[c]     + beta[c];
    float v1 = (h1 - mu) * rstd * gamma[c + 1] + beta[c + 1];
    size_t base = (size_t)r * DMODEL;
    *(float2*)(hn + base + c) = make_float2(v0, v1);
    hnh[(base >> 1) + tid] = f2h2(v0, v1);
}

// ---------------------------------------------------------------------------
extern "C" void kernel_launch(void* const* d_in, const int* in_sizes, int n_in,
                              void* d_out, int out_size)
{
    const float* x   = (const float*)d_in[0];
    const float* Wq  = (const float*)d_in[2];
    const float* bq  = (const float*)d_in[3];
    const float* Wk  = (const float*)d_in[4];
    const float* bk  = (const float*)d_in[5];
    const float* Wv  = (const float*)d_in[6];
    const float* bv  = (const float*)d_in[7];
    const float* lng = (const float*)d_in[14];
    const float* lnb = (const float*)d_in[15];
    const float* W1  = (const float*)d_in[16];
    const float* b1  = (const float*)d_in[17];
    const float* W2  = (const float*)d_in[18];
    const float* b2  = (const float*)d_in[19];

    uint32_t *pxh, *pWqkv, *pW1t, *pW2t, *phnh, *pacth, *pqkvh;
    float *pbqkv, *pattn, *phn;
    cudaGetSymbolAddress((void**)&pxh,    g_xh);
    cudaGetSymbolAddress((void**)&pWqkv,  g_Wqkv);
    cudaGetSymbolAddress((void**)&pW1t,   g_W1t);
    cudaGetSymbolAddress((void**)&pW2t,   g_W2t);
    cudaGetSymbolAddress((void**)&pbqkv,  g_bqkv);
    cudaGetSymbolAddress((void**)&pqkvh,  g_qkvh);
    cudaGetSymbolAddress((void**)&pattn,  g_attn);
    cudaGetSymbolAddress((void**)&phn,    g_hn);
    cudaGetSymbolAddress((void**)&phnh,   g_hnh);
    cudaGetSymbolAddress((void**)&pacth,  g_acth);

    cudaFuncSetAttribute((const void*)hgemm2<0,128>, cudaFuncAttributeMaxDynamicSharedMemorySize, GSMEM_128);
    cudaFuncSetAttribute((const void*)hgemm2<1,128>, cudaFuncAttributeMaxDynamicSharedMemorySize, GSMEM_128);
    cudaFuncSetAttribute((const void*)hgemm2<2,64>,  cudaFuncAttributeMaxDynamicSharedMemorySize, GSMEM_64);
    cudaFuncSetAttribute((const void*)attn_mma, cudaFuncAttributeMaxDynamicSharedMemorySize, ASMEM);

    dim3 blk(256);

    // 1: bias  2: x->fp16  3: QKV weight transpose
    prep_bias<<<(QKVN + 255) / 256, blk>>>(bq, bk, bv, pbqkv);
    prep_x<<<(int)(((size_t)MPAD * DMODEL / 2 + 255) / 256), blk>>>(x, pxh);
    prep_wqkv_t<<<dim3(8, 16, 3), blk>>>(Wq, Wk, Wv, pWqkv);

    // 4: fused QKV GEMM (ncu target slot)
    hgemm2<0,128><<<dim3(QKVN / 128, MPAD / 128), blk, GSMEM_128>>>(
        pxh, pWqkv, pbqkv, nullptr, nullptr, pqkvh, MPAD, QKVN, DMODEL);

    // 5: tensor-core attention
    attn_mma<<<dim3(SEQ / 64, NH, BATCH), dim3(128), ASMEM>>>(pqkvh, pattn);

    // 6: W1 transpose  7: residual + LN  8: W2 transpose
    prep_wt2<<<dim3(8, 64), blk>>>(W1, pW1t, DFF, 256);
    ln_kernel<<<MROWS, blk>>>(x, pattn, lng, lnb, phn, phnh);
    prep_wt2<<<dim3(32, 16), blk>>>(W2, pW2t, DMODEL, 1024);

    // 9: FFN up + gelu -> fp16
    hgemm2<1,128><<<dim3(DFF / 128, MPAD / 128), blk, GSMEM_128>>>(
        phnh, pW1t, b1, nullptr, nullptr, pacth, MROWS, DFF, DMODEL);

    // 10: FFN down + bias + residual -> out (BM=64: 512 CTAs, 3 CTAs/SM)
    hgemm2<2,64><<<dim3(DMODEL / 128, MPAD / 64), blk, GSMEM_64>>>(
        pacth, pW2t, b2, phn, (float*)d_out, nullptr, MROWS, DMODEL, DFF);
}

// round 15
// speedup vs baseline: 1.0518x; 1.0518x over previous
#include <cuda_runtime.h>
#include <cuda_fp16.h>
#include <math.h>
#include <stdint.h>

#define BATCH   2
#define S0      4095
#define SEQ     4096
#define DMODEL  512
#define NH      8
#define DH      64
#define DFF     2048
#define MROWS   (BATCH * S0)    // 8190
#define MPAD    (BATCH * SEQ)   // 8192
#define QKVN    1536
#define QKVW    768             // words per qkv row

// ---------------- scratch ----------------
__device__ __align__(16) uint32_t g_xh[(size_t)MPAD * DMODEL / 2];
__device__ __align__(16) uint32_t g_Wqkv[(size_t)QKVN * DMODEL / 2];
__device__ __align__(16) uint32_t g_W1t[(size_t)DFF * DMODEL / 2];
__device__ __align__(16) uint32_t g_W2t[(size_t)DMODEL * DFF / 2];
__device__ __align__(16) float    g_bqkv[QKVN];
__device__ __align__(16) uint32_t g_qkvh[(size_t)MPAD * QKVW];   // packed fp16
__device__ __align__(16) float    g_attn[(size_t)MPAD * DMODEL];
__device__ __align__(16) float    g_hn[(size_t)MROWS * DMODEL];
__device__ __align__(16) uint32_t g_hnh[(size_t)MROWS * DMODEL / 2];
__device__ __align__(16) uint32_t g_acth[(size_t)MROWS * DFF / 2];

__device__ __forceinline__ uint32_t smem_u32(const void* p) {
    uint32_t a;
    asm("{ .reg .u64 t; cvta.to.shared.u64 t, %1; cvt.u32.u64 %0, t; }"
        : "=r"(a) : "l"(p));
    return a;
}
__device__ __forceinline__ uint32_t f2h2(float a, float b) {
    __half2 h = __floats2half2_rn(a, b);
    return *(uint32_t*)&h;
}
__device__ __forceinline__ float2 h22f2(uint32_t w) {
    __half2 h = *(__half2*)&w;
    return __half22float2(h);
}
__device__ __forceinline__ float gelu_exact(float v) {
    return 0.5f * v * (1.0f + erff(v * 0.70710678118654752440f));
}
__device__ __forceinline__ void mma_f16(float* c, const uint32_t* a,
                                        const uint32_t* b) {
    asm volatile(
        "mma.sync.aligned.m16n8k16.row.col.f32.f16.f16.f32 "
        "{%0,%1,%2,%3}, {%4,%5,%6,%7}, {%8,%9}, {%0,%1,%2,%3};"
        : "+f"(c[0]), "+f"(c[1]), "+f"(c[2]), "+f"(c[3])
        : "r"(a[0]), "r"(a[1]), "r"(a[2]), "r"(a[3]), "r"(b[0]), "r"(b[1]));
}
#define LDSM4(r0, r1, r2, r3, addr) \
    asm volatile("ldmatrix.sync.aligned.m8n8.x4.shared.b16 {%0,%1,%2,%3}, [%4];" \
        : "=r"(r0), "=r"(r1), "=r"(r2), "=r"(r3) : "r"(addr))

__device__ __forceinline__ void cpa16(uint32_t dst, const void* src, bool v) {
    int sz = v ? 16 : 0;
    asm volatile("cp.async.cg.shared.global [%0], [%1], 16, %2;"
        :: "r"(dst), "l"(src), "r"(sz) : "memory");
}

// ---------------------------------------------------------------------------
// fp16 GEMM: C[M,N] = A[M,K] @ B[N,K]^T.  Block 128x128, warp tile 64x32
// (8 warps, 2m x 4n), BK=32, 4-stage cp.async (wait_group 2), stride-20-word
// SMEM, ldmatrix operands. 2 CTAs/SM (126 regs, 80KB smem).
// GEMM B addressing: lane bit3 -> k-offset, bit4 -> row+8, so B-frag pairs
// are {r0,r1} (rows0-7) and {r2,r3} (rows8-15)  [NOT the attn pairing].
// MODE 0: fp16x2 = acc + bias     MODE 1: fp16x2 = gelu(acc + bias)
// MODE 2: fp32   = acc + bias + res
// ---------------------------------------------------------------------------
#define STGW 5120                 // words per stage: A 2560 + B 2560
#define GSTAGES 4
#define GSMEM (GSTAGES * STGW * 4)   // 81920 bytes

template<int MODE>
__global__ __launch_bounds__(256, 2)
void hgemm2(const uint32_t* __restrict__ A, const uint32_t* __restrict__ B,
            const float* __restrict__ bias, const float* __restrict__ res,
            float* __restrict__ outf, uint32_t* __restrict__ outh,
            int M, int N, int K)
{
    extern __shared__ __align__(16) uint32_t S[];
    const uint32_t sm0 = smem_u32(S);
    const int tid  = threadIdx.x;
    const int lane = tid & 31;
    const int wid  = tid >> 5;
    const int wm   = wid & 1;       // 2 warp-rows x 64
    const int wn   = wid >> 1;      // 4 warp-cols x 32
    const int bn   = blockIdx.x;
    const int bm   = blockIdx.y;
    const int K2   = K >> 1;
    const int NT   = K >> 5;

    const int aRow = wm * 64 + (lane & 15);
    const int aW   = (lane >> 4) << 2;
    const int bRow = wn * 32 + (lane & 7) + ((lane >> 4) << 3);
    const int bW   = ((lane >> 3) & 1) << 2;

    auto load_stage = [&](int kt, int st) {
        const uint32_t base = sm0 + st * (STGW * 4);
#pragma unroll
        for (int i = 0; i < 4; i++) {
            int c = i * 256 + tid;          // 1024 chunks of 16B
            bool isA = (c < 512);
            int idx  = isA ? c : c - 512;
            int row  = idx >> 2, w = idx & 3;
            int grow = (isA ? bm : bn) * 128 + row;
            bool valid = (!isA) || (grow < M);
            const uint32_t* src = (isA ? A : B)
                + (size_t)(valid ? grow : 0) * K2 + kt * 16 + w * 4;
            uint32_t dst = base + ((isA ? 0 : 2560) + row * 20 + w * 4) * 4;
            cpa16(dst, src, valid);
        }
        asm volatile("cp.async.commit_group;" ::: "memory");
    };

    float acc[4][4][4];
#pragma unroll
    for (int i = 0; i < 4; i++)
#pragma unroll
        for (int j = 0; j < 4; j++)
#pragma unroll
            for (int q = 0; q < 4; q++) acc[i][j][q] = 0.0f;

    load_stage(0, 0);
    if (NT > 1) load_stage(1, 1);
    if (NT > 2) load_stage(2, 2);

    for (int kt = 0; kt < NT; kt++) {
        if (kt + 2 < NT)      asm volatile("cp.async.wait_group 2;" ::: "memory");
        else if (kt + 1 < NT) asm volatile("cp.async.wait_group 1;" ::: "memory");
        else                  asm volatile("cp.async.wait_group 0;" ::: "memory");
        __syncthreads();
        if (kt + 3 < NT) load_stage(kt + 3, (kt + 3) % GSTAGES);

        const uint32_t sA = sm0 + (kt % GSTAGES) * (STGW * 4);
        const uint32_t sB = sA + 2560 * 4;
#pragma unroll
        for (int kh = 0; kh < 2; kh++) {
            uint32_t a[4][4], b[4][2];
#pragma unroll
            for (int mf = 0; mf < 4; mf++) {
                uint32_t ad = sA + (((aRow + mf * 16) * 20) + aW + kh * 8) * 4;
                LDSM4(a[mf][0], a[mf][1], a[mf][2], a[mf][3], ad);
            }
#pragma unroll
            for (int bp = 0; bp < 2; bp++) {
                uint32_t ad = sB + (((bRow + bp * 16) * 20) + bW + kh * 8) * 4;
                LDSM4(b[2 * bp][0], b[2 * bp][1],
                      b[2 * bp + 1][0], b[2 * bp + 1][1], ad);
            }
#pragma unroll
            for (int mf = 0; mf < 4; mf++)
#pragma unroll
                for (int nf = 0; nf < 4; nf++)
                    mma_f16(acc[mf][nf], a[mf], b[nf]);
        }
    }

#pragma unroll
    for (int mf = 0; mf < 4; mf++) {
#pragma unroll
        for (int nf = 0; nf < 4; nf++) {
            const int r0  = bm * 128 + wm * 64 + mf * 16 + (lane >> 2);
            const int col = bn * 128 + wn * 32 + nf * 8 + (lane & 3) * 2;
            const float b0 = bias[col], b1 = bias[col + 1];
#pragma unroll
            for (int half = 0; half < 2; half++) {
                const int r = r0 + half * 8;
                if (r >= M) continue;
                float v0 = acc[mf][nf][half * 2 + 0] + b0;
                float v1 = acc[mf][nf][half * 2 + 1] + b1;
                if (MODE == 0) {
                    outh[(size_t)r * (N >> 1) + (col >> 1)] = f2h2(v0, v1);
                } else if (MODE == 1) {
                    outh[(size_t)r * (N >> 1) + (col >> 1)] =
                        f2h2(gelu_exact(v0), gelu_exact(v1));
                } else {
                    const float* rr = res + (size_t)r * N + col;
                    *(float2*)&outf[(size_t)r * N + col] =
                        make_float2(v0 + rr[0], v1 + rr[1]);
                }
            }
        }
    }
}

// ---------------------------------------------------------------------------
// prep kernels (coalesced transposes via SMEM tiles)
// ---------------------------------------------------------------------------
__global__ void prep_x(const float* __restrict__ x, uint32_t* __restrict__ o)
{
    size_t idx = (size_t)blockIdx.x * blockDim.x + threadIdx.x;
    if (idx >= (size_t)MPAD * DMODEL / 2) return;
    int r = (int)(idx >> 8), w = (int)(idx & 255);
    int s = r & (SEQ - 1), b = r >> 12;
    float v0 = 0.f, v1 = 0.f;
    if (s < S0) {
        const float* p = x + ((size_t)b * S0 + s) * DMODEL + 2 * w;
        v0 = p[0]; v1 = p[1];
    }
    o[idx] = f2h2(v0, v1);
}

__device__ __forceinline__ void wt_tile(const float* __restrict__ W,
                                        uint32_t* __restrict__ o,
                                        int N, int dstStride, int dstRowOff,
                                        float scale, int k0, int n0)
{
    __shared__ float ts[64][33];
    const int tid = threadIdx.x;
#pragma unroll
    for (int i = 0; i < 8; i++) {
        int t = i * 256 + tid;
        int kr = t >> 5, nc = t & 31;
        ts[kr][nc] = W[(size_t)(k0 + kr) * N + n0 + nc];
    }
    __syncthreads();
#pragma unroll
    for (int i = 0; i < 4; i++) {
        int t = i * 256 + tid;
        int n = t >> 5, w = t & 31;
        o[(size_t)(dstRowOff + n0 + n) * dstStride + (k0 >> 1) + w] =
            f2h2(ts[2 * w][n] * scale, ts[2 * w + 1][n] * scale);
    }
}

__global__ __launch_bounds__(256)
void prep_wqkv_t(const float* __restrict__ Wq, const float* __restrict__ Wk,
                 const float* __restrict__ Wv, uint32_t* __restrict__ o)
{
    const int z = blockIdx.z;
    const float* W = (z == 0) ? Wq : (z == 1) ? Wk : Wv;
    float sc = (z == 0) ? 0.125f : 1.0f;
    wt_tile(W, o, DMODEL, 256, z * 512, sc, blockIdx.x * 64, blockIdx.y * 32);
}

__global__ __launch_bounds__(256)
void prep_wt2(const float* __restrict__ W, uint32_t* __restrict__ o,
              int N, int dstStride)
{
    wt_tile(W, o, N, dstStride, 0, 1.0f, blockIdx.x * 64, blockIdx.y * 32);
}

__global__ void prep_bias(const float* __restrict__ bq, const float* __restrict__ bk,
                          const float* __restrict__ bv, float* __restrict__ o)
{
    int n = blockIdx.x * blockDim.x + threadIdx.x;
    if (n >= QKVN) return;
    o[n] = (n < 512) ? bq[n] * 0.125f
         : (n < 1024) ? bk[n - 512] : bv[n - 1024];
}

// ---------------------------------------------------------------------------
// Tensor-core sliding-window attention. Now 2 CTAs/SM (194.5KB smem/SM).
// Its ldmatrix addressing differs from the GEMM: B pairing {r0,r2} correct.
// ---------------------------------------------------------------------------
#define AQ0 0
#define AK0 (64 * 72)
#define AV0 (AK0 + 320 * 72)
#define ASMEMH (AV0 + 64 * 328)
#define ASMEM (ASMEMH * 2)

__global__ __launch_bounds__(128, 2)
void attn_mma(const uint32_t* __restrict__ qkvh, float* __restrict__ out)
{
    extern __shared__ __align__(16) unsigned short SH[];
    const uint32_t sb = smem_u32(SH);
    const int tid  = threadIdx.x;
    const int lane = tid & 31;
    const int w    = tid >> 5;
    const int h    = blockIdx.y;
    const int b    = blockIdx.z;
    const int t0   = blockIdx.x * 64;
    const size_t rowbase = (size_t)b * SEQ;

#pragma unroll
    for (int i = 0; i < 4; i++) {
        int c = i * 128 + tid;
        int row = c >> 3, c16 = c & 7;
        const uint32_t* src = qkvh + (rowbase + t0 + row) * QKVW + h * 32 + c16 * 4;
        *(uint4*)&SH[AQ0 + row * 72 + c16 * 8] = *(const uint4*)src;
    }
#pragma unroll
    for (int i = 0; i < 20; i++) {
        int c = i * 128 + tid;
        int row = c >> 3, c16 = c & 7;
        int key = t0 - 128 + row;
        key = key < 0 ? 0 : (key > SEQ - 1 ? SEQ - 1 : key);
        const uint32_t* src = qkvh + (rowbase + key) * QKVW + 256 + h * 32 + c16 * 4;
        *(uint4*)&SH[AK0 + row * 72 + c16 * 8] = *(const uint4*)src;
    }
#pragma unroll
    for (int i = 0; i < 20; i++) {
        int c = i * 128 + tid;
        int row = c >> 3, c16 = c & 7;
        int key = t0 - 128 + row;
        key = key < 0 ? 0 : (key > SEQ - 1 ? SEQ - 1 : key);
        const uint32_t* src = qkvh + (rowbase + key) * QKVW + 512 + h * 32 + c16 * 4;
        uint4 v = *(const uint4*)src;
        const unsigned short* hv = (const unsigned short*)&v;
#pragma unroll
        for (int j = 0; j < 8; j++)
            SH[AV0 + (c16 * 8 + j) * 328 + row] = hv[j];
    }
    __syncthreads();

    const int l15 = lane & 15;
    const int lh8 = (lane >> 4) << 3;
    const int kl0 = (lane & 3) << 1;
    const int r   = 16 * w + (lane >> 2);

    uint32_t aq[4][4];
#pragma unroll
    for (int j = 0; j < 4; j++) {
        uint32_t ad = sb + ((16 * w + l15) * 72 + 16 * j + lh8) * 2;
        LDSM4(aq[j][0], aq[j][1], aq[j][2], aq[j][3], ad);
    }

    float od[8][4];
#pragma unroll
    for (int nf = 0; nf < 8; nf++)
#pragma unroll
        for (int q = 0; q < 4; q++) od[nf][q] = 0.0f;
    float m0 = -1e30f, m1 = -1e30f, l0 = 0.f, l1 = 0.f;

    for (int c = 0; c < 5; c++) {
        const int ks = t0 - 128 + 64 * c;
        if (ks + 63 < 0 || ks > S0 - 1) continue;

        float sc[8][4];
#pragma unroll
        for (int nf = 0; nf < 8; nf++)
#pragma unroll
            for (int q = 0; q < 4; q++) sc[nf][q] = 0.0f;

#pragma unroll
        for (int j = 0; j < 4; j++)
#pragma unroll
            for (int p = 0; p < 4; p++) {
                uint32_t r0, r1, r2, r3;
                uint32_t ad = sb + (AK0 + (c * 64 + 16 * p + l15) * 72
                                    + 16 * j + lh8) * 2;
                LDSM4(r0, r1, r2, r3, ad);
                uint32_t b0[2] = {r0, r2}, b1[2] = {r1, r3};
                mma_f16(sc[2 * p],     aq[j], b0);
                mma_f16(sc[2 * p + 1], aq[j], b1);
            }

        float mx0 = -1e30f, mx1 = -1e30f;
#pragma unroll
        for (int nf = 0; nf < 8; nf++) {
            int kl = 8 * nf + kl0;
            int u  = 64 * c + kl - r;
            int sg = ks + kl;
            bool k0ok = (sg >= 0) && (sg < S0);
            bool k1ok = (sg + 1 >= 0) && (sg + 1 < S0);
            bool v0 = k0ok && (u >= 0)     && (u <= 256);
            bool v1 = k1ok && (u + 1 >= 0) && (u + 1 <= 256);
            bool v2 = k0ok && (u - 8 >= 0) && (u - 8 <= 256);
            bool v3 = k1ok && (u - 7 >= 0) && (u - 7 <= 256);
            sc[nf][0] = v0 ? sc[nf][0] : -1e30f;
            sc[nf][1] = v1 ? sc[nf][1] : -1e30f;
            sc[nf][2] = v2 ? sc[nf][2] : -1e30f;
            sc[nf][3] = v3 ? sc[nf][3] : -1e30f;
            mx0 = fmaxf(mx0, fmaxf(sc[nf][0], sc[nf][1]));
            mx1 = fmaxf(mx1, fmaxf(sc[nf][2], sc[nf][3]));
        }
        mx0 = fmaxf(mx0, __shfl_xor_sync(0xffffffffu, mx0, 1));
        mx0 = fmaxf(mx0, __shfl_xor_sync(0xffffffffu, mx0, 2));
        mx1 = fmaxf(mx1, __shfl_xor_sync(0xffffffffu, mx1, 1));
        mx1 = fmaxf(mx1, __shfl_xor_sync(0xffffffffu, mx1, 2));

        float mn0 = fmaxf(m0, mx0), mn1 = fmaxf(m1, mx1);
        float s0 = __expf(m0 - mn0), s1 = __expf(m1 - mn1);
        float ls0 = 0.f, ls1 = 0.f;
        uint32_t pa[4][4];
#pragma unroll
        for (int nf = 0; nf < 8; nf++) {
            float e0 = __expf(sc[nf][0] - mn0);
            float e1 = __expf(sc[nf][1] - mn0);
            float e2 = __expf(sc[nf][2] - mn1);
            float e3 = __expf(sc[nf][3] - mn1);
            ls0 += e0 + e1; ls1 += e2 + e3;
            int j = nf >> 1, q = nf & 1;
            pa[j][2 * q]     = f2h2(e0, e1);
            pa[j][2 * q + 1] = f2h2(e2, e3);
        }
        ls0 += __shfl_xor_sync(0xffffffffu, ls0, 1);
        ls0 += __shfl_xor_sync(0xffffffffu, ls0, 2);
        ls1 += __shfl_xor_sync(0xffffffffu, ls1, 1);
        ls1 += __shfl_xor_sync(0xffffffffu, ls1, 2);
        l0 = l0 * s0 + ls0;
        l1 = l1 * s1 + ls1;
        m0 = mn0; m1 = mn1;
#pragma unroll
        for (int nf = 0; nf < 8; nf++) {
            od[nf][0] *= s0; od[nf][1] *= s0;
            od[nf][2] *= s1; od[nf][3] *= s1;
        }

#pragma unroll
        for (int j = 0; j < 4; j++)
#pragma unroll
            for (int p = 0; p < 4; p++) {
                uint32_t r0, r1, r2, r3;
                uint32_t ad = sb + (AV0 + (16 * p + l15) * 328
                                    + c * 64 + 16 * j + lh8) * 2;
                LDSM4(r0, r1, r2, r3, ad);
                uint32_t b0[2] = {r0, r2}, b1[2] = {r1, r3};
                mma_f16(od[2 * p],     pa[j], b0);
                mma_f16(od[2 * p + 1], pa[j], b1);
            }
    }

    {
        const uint32_t* kg = qkvh + (rowbase + SEQ - 1) * QKVW + 256 + h * 32
                           + (lane & 3) * 8;
        const uint32_t* q0 = (const uint32_t*)(SH + (size_t)(AQ0 + r * 72))
                           + (lane & 3) * 8;
        const uint32_t* q1 = (const uint32_t*)(SH + (size_t)(AQ0 + (r + 8) * 72))
                           + (lane & 3) * 8;
        float gs0 = 0.f, gs1 = 0.f;
#pragma unroll
        for (int i = 0; i < 8; i++) {
            float2 fk = h22f2(kg[i]);
            float2 f0 = h22f2(q0[i]);
            float2 f1 = h22f2(q1[i]);
            gs0 += f0.x * fk.x + f0.y * fk.y;
            gs1 += f1.x * fk.x + f1.y * fk.y;
        }
        gs0 += __shfl_xor_sync(0xffffffffu, gs0, 1);
        gs0 += __shfl_xor_sync(0xffffffffu, gs0, 2);
        gs1 += __shfl_xor_sync(0xffffffffu, gs1, 1);
        gs1 += __shfl_xor_sync(0xffffffffu, gs1, 2);

        float mn0 = fmaxf(m0, gs0), mn1 = fmaxf(m1, gs1);
        float s0 = __expf(m0 - mn0), s1 = __expf(m1 - mn1);
        float pg0 = __expf(gs0 - mn0), pg1 = __expf(gs1 - mn1);
        l0 = l0 * s0 + pg0;
        l1 = l1 * s1 + pg1;
        const uint32_t* vg = qkvh + (rowbase + SEQ - 1) * QKVW + 512 + h * 32
                           + (lane & 3);
#pragma unroll
        for (int nf = 0; nf < 8; nf++) {
            float2 fv = h22f2(vg[nf * 4]);
            od[nf][0] = od[nf][0] * s0 + pg0 * fv.x;
            od[nf][1] = od[nf][1] * s0 + pg0 * fv.y;
            od[nf][2] = od[nf][2] * s1 + pg1 * fv.x;
            od[nf][3] = od[nf][3] * s1 + pg1 * fv.y;
        }
    }

    const float inv0 = 1.0f / l0, inv1 = 1.0f / l1;
    const int t = t0 + r;
    float* o0 = out + ((size_t)b * SEQ + t) * DMODEL + h * DH + kl0;
    float* o1 = o0 + 8 * (size_t)DMODEL;
#pragma unroll
    for (int nf = 0; nf < 8; nf++) {
        *(float2*)(o0 + nf * 8) = make_float2(od[nf][0] * inv0, od[nf][1] * inv0);
        *(float2*)(o1 + nf * 8) = make_float2(od[nf][2] * inv1, od[nf][3] * inv1);
    }
}

// ---------------------------------------------------------------------------
// Residual + LayerNorm -> hn fp32 + packed fp16
// ---------------------------------------------------------------------------
__global__ __launch_bounds__(256)
void ln_kernel(const float* __restrict__ x, const float* __restrict__ attn,
               const float* __restrict__ gamma, const float* __restrict__ beta,
               float* __restrict__ hn, uint32_t* __restrict__ hnh)
{
    const int r = blockIdx.x;
    const int b = r / S0;
    const int s = r - b * S0;
    const int tid = threadIdx.x;
    const int c = tid * 2;

    float2 xv = *(const float2*)(x + (size_t)r * DMODEL + c);
    float2 av = *(const float2*)(attn + ((size_t)b * SEQ + s) * DMODEL + c);
    float h0 = xv.x + av.x;
    float h1 = xv.y + av.y;
    float sum = h0 + h1;
    float sq  = h0 * h0 + h1 * h1;
#pragma unroll
    for (int off = 16; off; off >>= 1) {
        sum += __shfl_xor_sync(0xffffffffu, sum, off);
        sq  += __shfl_xor_sync(0xffffffffu, sq,  off);
    }
    __shared__ float rs[8], rq[8];
    int w = tid >> 5, lane = tid & 31;
    if (lane == 0) { rs[w] = sum; rq[w] = sq; }
    __syncthreads();
    float ts = 0.f, tq = 0.f;
#pragma unroll
    for (int i = 0; i < 8; i++) { ts += rs[i]; tq += rq[i]; }
    float mu   = ts * (1.0f / DMODEL);
    float var  = tq * (1.0f / DMODEL) - mu * mu;
    float rstd = rsqrtf(var + 1e-5f);
    float v0 = (h0 - mu) * rstd * gamma[c]     + beta[c];
    float v1 = (h1 - mu) * rstd * gamma[c + 1] + beta[c + 1];
    size_t base = (size_t)r * DMODEL;
    *(float2*)(hn + base + c) = make_float2(v0, v1);
    hnh[(base >> 1) + tid] = f2h2(v0, v1);
}

// ---------------------------------------------------------------------------
extern "C" void kernel_launch(void* const* d_in, const int* in_sizes, int n_in,
                              void* d_out, int out_size)
{
    const float* x   = (const float*)d_in[0];
    const float* Wq  = (const float*)d_in[2];
    const float* bq  = (const float*)d_in[3];
    const float* Wk  = (const float*)d_in[4];
    const float* bk  = (const float*)d_in[5];
    const float* Wv  = (const float*)d_in[6];
    const float* bv  = (const float*)d_in[7];
    const float* lng = (const float*)d_in[14];
    const float* lnb = (const float*)d_in[15];
    const float* W1  = (const float*)d_in[16];
    const float* b1  = (const float*)d_in[17];
    const float* W2  = (const float*)d_in[18];
    const float* b2  = (const float*)d_in[19];

    uint32_t *pxh, *pWqkv, *pW1t, *pW2t, *phnh, *pacth, *pqkvh;
    float *pbqkv, *pattn, *phn;
    cudaGetSymbolAddress((void**)&pxh,    g_xh);
    cudaGetSymbolAddress((void**)&pWqkv,  g_Wqkv);
    cudaGetSymbolAddress((void**)&pW1t,   g_W1t);
    cudaGetSymbolAddress((void**)&pW2t,   g_W2t);
    cudaGetSymbolAddress((void**)&pbqkv,  g_bqkv);
    cudaGetSymbolAddress((void**)&pqkvh,  g_qkvh);
    cudaGetSymbolAddress((void**)&pattn,  g_attn);
    cudaGetSymbolAddress((void**)&phn,    g_hn);
    cudaGetSymbolAddress((void**)&phnh,   g_hnh);
    cudaGetSymbolAddress((void**)&pacth,  g_acth);

    cudaFuncSetAttribute(hgemm2<0>, cudaFuncAttributeMaxDynamicSharedMemorySize, GSMEM);
    cudaFuncSetAttribute(hgemm2<1>, cudaFuncAttributeMaxDynamicSharedMemorySize, GSMEM);
    cudaFuncSetAttribute(hgemm2<2>, cudaFuncAttributeMaxDynamicSharedMemorySize, GSMEM);
    cudaFuncSetAttribute(attn_mma,  cudaFuncAttributeMaxDynamicSharedMemorySize, ASMEM);

    dim3 blk(256);

    // 1: bias  2: x->fp16  3: QKV weight transpose
    prep_bias<<<(QKVN + 255) / 256, blk>>>(bq, bk, bv, pbqkv);
    prep_x<<<(int)(((size_t)MPAD * DMODEL / 2 + 255) / 256), blk>>>(x, pxh);
    prep_wqkv_t<<<dim3(8, 16, 3), blk>>>(Wq, Wk, Wv, pWqkv);

    // 4: fused QKV GEMM (ncu target slot)
    hgemm2<0><<<dim3(QKVN / 128, MPAD / 128), blk, GSMEM>>>(
        pxh, pWqkv, pbqkv, nullptr, nullptr, pqkvh, MPAD, QKVN, DMODEL);

    // 5: tensor-core attention (2 CTAs/SM)
    attn_mma<<<dim3(SEQ / 64, NH, BATCH), dim3(128), ASMEM>>>(pqkvh, pattn);

    // 6: W1 transpose  7: residual + LN  8: W2 transpose
    prep_wt2<<<dim3(8, 64), blk>>>(W1, pW1t, DFF, 256);
    ln_kernel<<<MROWS, blk>>>(x, pattn, lng, lnb, phn, phnh);
    prep_wt2<<<dim3(32, 16), blk>>>(W2, pW2t, DMODEL, 1024);

    // 9: FFN up + gelu -> fp16
    hgemm2<1><<<dim3(DFF / 128, MPAD / 128), blk, GSMEM>>>(
        phnh, pW1t, b1, nullptr, nullptr, pacth, MROWS, DFF, DMODEL);

    // 10: FFN down + bias + residual -> out
    hgemm2<2><<<dim3(DMODEL / 128, MPAD / 128), blk, GSMEM>>>(
        pacth, pW2t, b2, phn, (float*)d_out, nullptr, MROWS, DMODEL, DFF);
}

// round 16
// speedup vs baseline: 1.0654x; 1.0129x over previous
#include <cuda_runtime.h>
#include <cuda_fp16.h>
#include <math.h>
#include <stdint.h>

#define BATCH   2
#define S0      4095
#define SEQ     4096
#define DMODEL  512
#define NH      8
#define DH      64
#define DFF     2048
#define MROWS   (BATCH * S0)    // 8190
#define MPAD    (BATCH * SEQ)   // 8192
#define QKVN    1536
#define QKVW    768             // words per qkv row

// ---------------- scratch ----------------
__device__ __align__(16) uint32_t g_xh[(size_t)MPAD * DMODEL / 2];
__device__ __align__(16) uint32_t g_Wqkv[(size_t)QKVN * DMODEL / 2];
__device__ __align__(16) uint32_t g_W1t[(size_t)DFF * DMODEL / 2];
__device__ __align__(16) uint32_t g_W2t[(size_t)DMODEL * DFF / 2];
__device__ __align__(16) float    g_bqkv[QKVN];
__device__ __align__(16) uint32_t g_qkvh[(size_t)MPAD * QKVW];   // packed fp16
__device__ __align__(16) float    g_attn[(size_t)MPAD * DMODEL];
__device__ __align__(16) float    g_hn[(size_t)MROWS * DMODEL];
__device__ __align__(16) uint32_t g_hnh[(size_t)MROWS * DMODEL / 2];
__device__ __align__(16) uint32_t g_acth[(size_t)MROWS * DFF / 2];

__device__ __forceinline__ uint32_t smem_u32(const void* p) {
    uint32_t a;
    asm("{ .reg .u64 t; cvta.to.shared.u64 t, %1; cvt.u32.u64 %0, t; }"
        : "=r"(a) : "l"(p));
    return a;
}
__device__ __forceinline__ uint32_t f2h2(float a, float b) {
    __half2 h = __floats2half2_rn(a, b);
    return *(uint32_t*)&h;
}
__device__ __forceinline__ float2 h22f2(uint32_t w) {
    __half2 h = *(__half2*)&w;
    return __half22float2(h);
}
__device__ __forceinline__ float gelu_exact(float v) {
    return 0.5f * v * (1.0f + erff(v * 0.70710678118654752440f));
}
__device__ __forceinline__ void mma_f16(float* c, const uint32_t* a,
                                        const uint32_t* b) {
    asm volatile(
        "mma.sync.aligned.m16n8k16.row.col.f32.f16.f16.f32 "
        "{%0,%1,%2,%3}, {%4,%5,%6,%7}, {%8,%9}, {%0,%1,%2,%3};"
        : "+f"(c[0]), "+f"(c[1]), "+f"(c[2]), "+f"(c[3])
        : "r"(a[0]), "r"(a[1]), "r"(a[2]), "r"(a[3]), "r"(b[0]), "r"(b[1]));
}
#define LDSM4(r0, r1, r2, r3, addr) \
    asm volatile("ldmatrix.sync.aligned.m8n8.x4.shared.b16 {%0,%1,%2,%3}, [%4];" \
        : "=r"(r0), "=r"(r1), "=r"(r2), "=r"(r3) : "r"(addr))

__device__ __forceinline__ void cpa16(uint32_t dst, const void* src, bool v) {
    int sz = v ? 16 : 0;
    asm volatile("cp.async.cg.shared.global [%0], [%1], 16, %2;"
        :: "r"(dst), "l"(src), "r"(sz) : "memory");
}

// ---------------------------------------------------------------------------
// Persistent fp16 GEMM: C[M,N] = A[M,K] @ B[N,K]^T.  Block 128x128 tile,
// warp tile 64x32 (8 warps 2m x 4n), BK=32, 4-stage cp.async, ldmatrix.
// Each CTA grid-strides over output tiles (removes wave-quantization tail).
// B-frag pairs {r0,r1}/{r2,r3} per GEMM addressing (bit3->k, bit4->row+8).
// MODE 0: fp16x2 = acc + bias     MODE 1: fp16x2 = gelu(acc + bias)
// MODE 2: fp32   = acc + bias + res
// ---------------------------------------------------------------------------
#define STGW 5120
#define GSTAGES 4
#define GSMEM (GSTAGES * STGW * 4)   // 81920 bytes

template<int MODE>
__global__ __launch_bounds__(256, 2)
void hgemm2(const uint32_t* __restrict__ A, const uint32_t* __restrict__ B,
            const float* __restrict__ bias, const float* __restrict__ res,
            float* __restrict__ outf, uint32_t* __restrict__ outh,
            int M, int N, int K)
{
    extern __shared__ __align__(16) uint32_t S[];
    const uint32_t sm0 = smem_u32(S);
    const int tid  = threadIdx.x;
    const int lane = tid & 31;
    const int wid  = tid >> 5;
    const int wm   = wid & 1;
    const int wn   = wid >> 1;
    const int K2   = K >> 1;
    const int NT   = K >> 5;
    const int nbn  = N >> 7;
    const int nTiles = ((M + 127) >> 7) * nbn;

    const int aRow = wm * 64 + (lane & 15);
    const int aW   = (lane >> 4) << 2;
    const int bRow = wn * 32 + (lane & 7) + ((lane >> 4) << 3);
    const int bW   = ((lane >> 3) & 1) << 2;

    for (int tix = blockIdx.x; tix < nTiles; tix += gridDim.x) {
        const int bm = tix / nbn;
        const int bn = tix - bm * nbn;

        auto load_stage = [&](int kt, int st) {
            const uint32_t base = sm0 + st * (STGW * 4);
#pragma unroll
            for (int i = 0; i < 4; i++) {
                int c = i * 256 + tid;
                bool isA = (c < 512);
                int idx  = isA ? c : c - 512;
                int row  = idx >> 2, w = idx & 3;
                int grow = (isA ? bm : bn) * 128 + row;
                bool valid = (!isA) || (grow < M);
                const uint32_t* src = (isA ? A : B)
                    + (size_t)(valid ? grow : 0) * K2 + kt * 16 + w * 4;
                uint32_t dst = base + ((isA ? 0 : 2560) + row * 20 + w * 4) * 4;
                cpa16(dst, src, valid);
            }
            asm volatile("cp.async.commit_group;" ::: "memory");
        };

        float acc[4][4][4];
#pragma unroll
        for (int i = 0; i < 4; i++)
#pragma unroll
            for (int j = 0; j < 4; j++)
#pragma unroll
                for (int q = 0; q < 4; q++) acc[i][j][q] = 0.0f;

        load_stage(0, 0);
        load_stage(1, 1);
        load_stage(2, 2);

        for (int kt = 0; kt < NT; kt++) {
            if (kt + 2 < NT)      asm volatile("cp.async.wait_group 2;" ::: "memory");
            else if (kt + 1 < NT) asm volatile("cp.async.wait_group 1;" ::: "memory");
            else                  asm volatile("cp.async.wait_group 0;" ::: "memory");
            __syncthreads();
            if (kt + 3 < NT) load_stage(kt + 3, (kt + 3) % GSTAGES);

            const uint32_t sA = sm0 + (kt % GSTAGES) * (STGW * 4);
            const uint32_t sB = sA + 2560 * 4;
#pragma unroll
            for (int kh = 0; kh < 2; kh++) {
                uint32_t a[4][4], b[4][2];
#pragma unroll
                for (int mf = 0; mf < 4; mf++) {
                    uint32_t ad = sA + (((aRow + mf * 16) * 20) + aW + kh * 8) * 4;
                    LDSM4(a[mf][0], a[mf][1], a[mf][2], a[mf][3], ad);
                }
#pragma unroll
                for (int bp = 0; bp < 2; bp++) {
                    uint32_t ad = sB + (((bRow + bp * 16) * 20) + bW + kh * 8) * 4;
                    LDSM4(b[2 * bp][0], b[2 * bp][1],
                          b[2 * bp + 1][0], b[2 * bp + 1][1], ad);
                }
#pragma unroll
                for (int mf = 0; mf < 4; mf++)
#pragma unroll
                    for (int nf = 0; nf < 4; nf++)
                        mma_f16(acc[mf][nf], a[mf], b[nf]);
            }
        }

#pragma unroll
        for (int mf = 0; mf < 4; mf++) {
#pragma unroll
            for (int nf = 0; nf < 4; nf++) {
                const int r0  = bm * 128 + wm * 64 + mf * 16 + (lane >> 2);
                const int col = bn * 128 + wn * 32 + nf * 8 + (lane & 3) * 2;
                const float b0 = bias[col], b1 = bias[col + 1];
#pragma unroll
                for (int half = 0; half < 2; half++) {
                    const int r = r0 + half * 8;
                    if (r >= M) continue;
                    float v0 = acc[mf][nf][half * 2 + 0] + b0;
                    float v1 = acc[mf][nf][half * 2 + 1] + b1;
                    if (MODE == 0) {
                        outh[(size_t)r * (N >> 1) + (col >> 1)] = f2h2(v0, v1);
                    } else if (MODE == 1) {
                        outh[(size_t)r * (N >> 1) + (col >> 1)] =
                            f2h2(gelu_exact(v0), gelu_exact(v1));
                    } else {
                        const float* rr = res + (size_t)r * N + col;
                        *(float2*)&outf[(size_t)r * N + col] =
                            make_float2(v0 + rr[0], v1 + rr[1]);
                    }
                }
            }
        }
    }
}

// ---------------------------------------------------------------------------
// prep kernels
// ---------------------------------------------------------------------------
__global__ void prep_x(const float* __restrict__ x, uint32_t* __restrict__ o)
{
    size_t idx = (size_t)blockIdx.x * blockDim.x + threadIdx.x;
    if (idx >= (size_t)MPAD * DMODEL / 2) return;
    int r = (int)(idx >> 8), w = (int)(idx & 255);
    int s = r & (SEQ - 1), b = r >> 12;
    float v0 = 0.f, v1 = 0.f;
    if (s < S0) {
        const float* p = x + ((size_t)b * S0 + s) * DMODEL + 2 * w;
        v0 = p[0]; v1 = p[1];
    }
    o[idx] = f2h2(v0, v1);
}

__device__ __forceinline__ void wt_tile(const float* __restrict__ W,
                                        uint32_t* __restrict__ o,
                                        int N, int dstStride, int dstRowOff,
                                        float scale, int k0, int n0)
{
    __shared__ float ts[64][33];
    const int tid = threadIdx.x;
#pragma unroll
    for (int i = 0; i < 8; i++) {
        int t = i * 256 + tid;
        int kr = t >> 5, nc = t & 31;
        ts[kr][nc] = W[(size_t)(k0 + kr) * N + n0 + nc];
    }
    __syncthreads();
#pragma unroll
    for (int i = 0; i < 4; i++) {
        int t = i * 256 + tid;
        int n = t >> 5, w = t & 31;
        o[(size_t)(dstRowOff + n0 + n) * dstStride + (k0 >> 1) + w] =
            f2h2(ts[2 * w][n] * scale, ts[2 * w + 1][n] * scale);
    }
}

// QKV weight transpose + (block 0 of z==0 also writes the fused bias)
__global__ __launch_bounds__(256)
void prep_wqkv_t(const float* __restrict__ Wq, const float* __restrict__ Wk,
                 const float* __restrict__ Wv,
                 const float* __restrict__ bq, const float* __restrict__ bk,
                 const float* __restrict__ bv,
                 uint32_t* __restrict__ o, float* __restrict__ obias)
{
    const int z = blockIdx.z;
    const float* W = (z == 0) ? Wq : (z == 1) ? Wk : Wv;
    float sc = (z == 0) ? 0.125f : 1.0f;
    wt_tile(W, o, DMODEL, 256, z * 512, sc, blockIdx.x * 64, blockIdx.y * 32);
    if (z == 0 && blockIdx.x == 0 && blockIdx.y == 0) {
#pragma unroll
        for (int i = 0; i < 6; i++) {
            int n = i * 256 + threadIdx.x;
            obias[n] = (n < 512) ? bq[n] * 0.125f
                     : (n < 1024) ? bk[n - 512] : bv[n - 1024];
        }
    }
}

// W1 + W2 transposes in a single launch (flattened grid: 512 + 512 tiles)
__global__ __launch_bounds__(256)
void prep_w12(const float* __restrict__ W1, const float* __restrict__ W2,
              uint32_t* __restrict__ o1, uint32_t* __restrict__ o2)
{
    int bid = blockIdx.x;
    if (bid < 512) {          // W1 [512, 2048]: 8 k-tiles x 64 n-tiles
        int kIdx = bid >> 6, nIdx = bid & 63;
        wt_tile(W1, o1, DFF, 256, 0, 1.0f, kIdx * 64, nIdx * 32);
    } else {                  // W2 [2048, 512]: 32 k-tiles x 16 n-tiles
        int b2 = bid - 512;
        int kIdx = b2 >> 4, nIdx = b2 & 15;
        wt_tile(W2, o2, DMODEL, 1024, 0, 1.0f, kIdx * 64, nIdx * 32);
    }
}

// ---------------------------------------------------------------------------
// Tensor-core sliding-window attention (proven; B pairing {r0,r2} for ITS
// addressing scheme). 2 CTAs/SM.
// ---------------------------------------------------------------------------
#define AQ0 0
#define AK0 (64 * 72)
#define AV0 (AK0 + 320 * 72)
#define ASMEMH (AV0 + 64 * 328)
#define ASMEM (ASMEMH * 2)

__global__ __launch_bounds__(128, 2)
void attn_mma(const uint32_t* __restrict__ qkvh, float* __restrict__ out)
{
    extern __shared__ __align__(16) unsigned short SH[];
    const uint32_t sb = smem_u32(SH);
    const int tid  = threadIdx.x;
    const int lane = tid & 31;
    const int w    = tid >> 5;
    const int h    = blockIdx.y;
    const int b    = blockIdx.z;
    const int t0   = blockIdx.x * 64;
    const size_t rowbase = (size_t)b * SEQ;

#pragma unroll
    for (int i = 0; i < 4; i++) {
        int c = i * 128 + tid;
        int row = c >> 3, c16 = c & 7;
        const uint32_t* src = qkvh + (rowbase + t0 + row) * QKVW + h * 32 + c16 * 4;
        *(uint4*)&SH[AQ0 + row * 72 + c16 * 8] = *(const uint4*)src;
    }
#pragma unroll
    for (int i = 0; i < 20; i++) {
        int c = i * 128 + tid;
        int row = c >> 3, c16 = c & 7;
        int key = t0 - 128 + row;
        key = key < 0 ? 0 : (key > SEQ - 1 ? SEQ - 1 : key);
        const uint32_t* src = qkvh + (rowbase + key) * QKVW + 256 + h * 32 + c16 * 4;
        *(uint4*)&SH[AK0 + row * 72 + c16 * 8] = *(const uint4*)src;
    }
#pragma unroll
    for (int i = 0; i < 20; i++) {
        int c = i * 128 + tid;
        int row = c >> 3, c16 = c & 7;
        int key = t0 - 128 + row;
        key = key < 0 ? 0 : (key > SEQ - 1 ? SEQ - 1 : key);
        const uint32_t* src = qkvh + (rowbase + key) * QKVW + 512 + h * 32 + c16 * 4;
        uint4 v = *(const uint4*)src;
        const unsigned short* hv = (const unsigned short*)&v;
#pragma unroll
        for (int j = 0; j < 8; j++)
            SH[AV0 + (c16 * 8 + j) * 328 + row] = hv[j];
    }
    __syncthreads();

    const int l15 = lane & 15;
    const int lh8 = (lane >> 4) << 3;
    const int kl0 = (lane & 3) << 1;
    const int r   = 16 * w + (lane >> 2);

    uint32_t aq[4][4];
#pragma unroll
    for (int j = 0; j < 4; j++) {
        uint32_t ad = sb + ((16 * w + l15) * 72 + 16 * j + lh8) * 2;
        LDSM4(aq[j][0], aq[j][1], aq[j][2], aq[j][3], ad);
    }

    float od[8][4];
#pragma unroll
    for (int nf = 0; nf < 8; nf++)
#pragma unroll
        for (int q = 0; q < 4; q++) od[nf][q] = 0.0f;
    float m0 = -1e30f, m1 = -1e30f, l0 = 0.f, l1 = 0.f;

    for (int c = 0; c < 5; c++) {
        const int ks = t0 - 128 + 64 * c;
        if (ks + 63 < 0 || ks > S0 - 1) continue;

        float sc[8][4];
#pragma unroll
        for (int nf = 0; nf < 8; nf++)
#pragma unroll
            for (int q = 0; q < 4; q++) sc[nf][q] = 0.0f;

#pragma unroll
        for (int j = 0; j < 4; j++)
#pragma unroll
            for (int p = 0; p < 4; p++) {
                uint32_t r0, r1, r2, r3;
                uint32_t ad = sb + (AK0 + (c * 64 + 16 * p + l15) * 72
                                    + 16 * j + lh8) * 2;
                LDSM4(r0, r1, r2, r3, ad);
                uint32_t b0[2] = {r0, r2}, b1[2] = {r1, r3};
                mma_f16(sc[2 * p],     aq[j], b0);
                mma_f16(sc[2 * p + 1], aq[j], b1);
            }

        float mx0 = -1e30f, mx1 = -1e30f;
#pragma unroll
        for (int nf = 0; nf < 8; nf++) {
            int kl = 8 * nf + kl0;
            int u  = 64 * c + kl - r;
            int sg = ks + kl;
            bool k0ok = (sg >= 0) && (sg < S0);
            bool k1ok = (sg + 1 >= 0) && (sg + 1 < S0);
            bool v0 = k0ok && (u >= 0)     && (u <= 256);
            bool v1 = k1ok && (u + 1 >= 0) && (u + 1 <= 256);
            bool v2 = k0ok && (u - 8 >= 0) && (u - 8 <= 256);
            bool v3 = k1ok && (u - 7 >= 0) && (u - 7 <= 256);
            sc[nf][0] = v0 ? sc[nf][0] : -1e30f;
            sc[nf][1] = v1 ? sc[nf][1] : -1e30f;
            sc[nf][2] = v2 ? sc[nf][2] : -1e30f;
            sc[nf][3] = v3 ? sc[nf][3] : -1e30f;
            mx0 = fmaxf(mx0, fmaxf(sc[nf][0], sc[nf][1]));
            mx1 = fmaxf(mx1, fmaxf(sc[nf][2], sc[nf][3]));
        }
        mx0 = fmaxf(mx0, __shfl_xor_sync(0xffffffffu, mx0, 1));
        mx0 = fmaxf(mx0, __shfl_xor_sync(0xffffffffu, mx0, 2));
        mx1 = fmaxf(mx1, __shfl_xor_sync(0xffffffffu, mx1, 1));
        mx1 = fmaxf(mx1, __shfl_xor_sync(0xffffffffu, mx1, 2));

        float mn0 = fmaxf(m0, mx0), mn1 = fmaxf(m1, mx1);
        float s0 = __expf(m0 - mn0), s1 = __expf(m1 - mn1);
        float ls0 = 0.f, ls1 = 0.f;
        uint32_t pa[4][4];
#pragma unroll
        for (int nf = 0; nf < 8; nf++) {
            float e0 = __expf(sc[nf][0] - mn0);
            float e1 = __expf(sc[nf][1] - mn0);
            float e2 = __expf(sc[nf][2] - mn1);
            float e3 = __expf(sc[nf][3] - mn1);
            ls0 += e0 + e1; ls1 += e2 + e3;
            int j = nf >> 1, q = nf & 1;
            pa[j][2 * q]     = f2h2(e0, e1);
            pa[j][2 * q + 1] = f2h2(e2, e3);
        }
        ls0 += __shfl_xor_sync(0xffffffffu, ls0, 1);
        ls0 += __shfl_xor_sync(0xffffffffu, ls0, 2);
        ls1 += __shfl_xor_sync(0xffffffffu, ls1, 1);
        ls1 += __shfl_xor_sync(0xffffffffu, ls1, 2);
        l0 = l0 * s0 + ls0;
        l1 = l1 * s1 + ls1;
        m0 = mn0; m1 = mn1;
#pragma unroll
        for (int nf = 0; nf < 8; nf++) {
            od[nf][0] *= s0; od[nf][1] *= s0;
            od[nf][2] *= s1; od[nf][3] *= s1;
        }

#pragma unroll
        for (int j = 0; j < 4; j++)
#pragma unroll
            for (int p = 0; p < 4; p++) {
                uint32_t r0, r1, r2, r3;
                uint32_t ad = sb + (AV0 + (16 * p + l15) * 328
                                    + c * 64 + 16 * j + lh8) * 2;
                LDSM4(r0, r1, r2, r3, ad);
                uint32_t b0[2] = {r0, r2}, b1[2] = {r1, r3};
                mma_f16(od[2 * p],     pa[j], b0);
                mma_f16(od[2 * p + 1], pa[j], b1);
            }
    }

    {
        const uint32_t* kg = qkvh + (rowbase + SEQ - 1) * QKVW + 256 + h * 32
                           + (lane & 3) * 8;
        const uint32_t* q0 = (const uint32_t*)(SH + (size_t)(AQ0 + r * 72))
                           + (lane & 3) * 8;
        const uint32_t* q1 = (const uint32_t*)(SH + (size_t)(AQ0 + (r + 8) * 72))
                           + (lane & 3) * 8;
        float gs0 = 0.f, gs1 = 0.f;
#pragma unroll
        for (int i = 0; i < 8; i++) {
            float2 fk = h22f2(kg[i]);
            float2 f0 = h22f2(q0[i]);
            float2 f1 = h22f2(q1[i]);
            gs0 += f0.x * fk.x + f0.y * fk.y;
            gs1 += f1.x * fk.x + f1.y * fk.y;
        }
        gs0 += __shfl_xor_sync(0xffffffffu, gs0, 1);
        gs0 += __shfl_xor_sync(0xffffffffu, gs0, 2);
        gs1 += __shfl_xor_sync(0xffffffffu, gs1, 1);
        gs1 += __shfl_xor_sync(0xffffffffu, gs1, 2);

        float mn0 = fmaxf(m0, gs0), mn1 = fmaxf(m1, gs1);
        float s0 = __expf(m0 - mn0), s1 = __expf(m1 - mn1);
        float pg0 = __expf(gs0 - mn0), pg1 = __expf(gs1 - mn1);
        l0 = l0 * s0 + pg0;
        l1 = l1 * s1 + pg1;
        const uint32_t* vg = qkvh + (rowbase + SEQ - 1) * QKVW + 512 + h * 32
                           + (lane & 3);
#pragma unroll
        for (int nf = 0; nf < 8; nf++) {
            float2 fv = h22f2(vg[nf * 4]);
            od[nf][0] = od[nf][0] * s0 + pg0 * fv.x;
            od[nf][1] = od[nf][1] * s0 + pg0 * fv.y;
            od[nf][2] = od[nf][2] * s1 + pg1 * fv.x;
            od[nf][3] = od[nf][3] * s1 + pg1 * fv.y;
        }
    }

    const float inv0 = 1.0f / l0, inv1 = 1.0f / l1;
    const int t = t0 + r;
    float* o0 = out + ((size_t)b * SEQ + t) * DMODEL + h * DH + kl0;
    float* o1 = o0 + 8 * (size_t)DMODEL;
#pragma unroll
    for (int nf = 0; nf < 8; nf++) {
        *(float2*)(o0 + nf * 8) = make_float2(od[nf][0] * inv0, od[nf][1] * inv0);
        *(float2*)(o1 + nf * 8) = make_float2(od[nf][2] * inv1, od[nf][3] * inv1);
    }
}

// ---------------------------------------------------------------------------
// Residual + LayerNorm -> hn fp32 + packed fp16
// ---------------------------------------------------------------------------
__global__ __launch_bounds__(256)
void ln_kernel(const float* __restrict__ x, const float* __restrict__ attn,
               const float* __restrict__ gamma, const float* __restrict__ beta,
               float* __restrict__ hn, uint32_t* __restrict__ hnh)
{
    const int r = blockIdx.x;
    const int b = r / S0;
    const int s = r - b * S0;
    const int tid = threadIdx.x;
    const int c = tid * 2;

    float2 xv = *(const float2*)(x + (size_t)r * DMODEL + c);
    float2 av = *(const float2*)(attn + ((size_t)b * SEQ + s) * DMODEL + c);
    float h0 = xv.x + av.x;
    float h1 = xv.y + av.y;
    float sum = h0 + h1;
    float sq  = h0 * h0 + h1 * h1;
#pragma unroll
    for (int off = 16; off; off >>= 1) {
        sum += __shfl_xor_sync(0xffffffffu, sum, off);
        sq  += __shfl_xor_sync(0xffffffffu, sq,  off);
    }
    __shared__ float rs[8], rq[8];
    int w = tid >> 5, lane = tid & 31;
    if (lane == 0) { rs[w] = sum; rq[w] = sq; }
    __syncthreads();
    float ts = 0.f, tq = 0.f;
#pragma unroll
    for (int i = 0; i < 8; i++) { ts += rs[i]; tq += rq[i]; }
    float mu   = ts * (1.0f / DMODEL);
    float var  = tq * (1.0f / DMODEL) - mu * mu;
    float rstd = rsqrtf(var + 1e-5f);
    float v0 = (h0 - mu) * rstd * gamma[c]     + beta[c];
    float v1 = (h1 - mu) * rstd * gamma[c + 1] + beta[c + 1];
    size_t base = (size_t)r * DMODEL;
    *(float2*)(hn + base + c) = make_float2(v0, v1);
    hnh[(base >> 1) + tid] = f2h2(v0, v1);
}

// ---------------------------------------------------------------------------
extern "C" void kernel_launch(void* const* d_in, const int* in_sizes, int n_in,
                              void* d_out, int out_size)
{
    const float* x   = (const float*)d_in[0];
    const float* Wq  = (const float*)d_in[2];
    const float* bq  = (const float*)d_in[3];
    const float* Wk  = (const float*)d_in[4];
    const float* bk  = (const float*)d_in[5];
    const float* Wv  = (const float*)d_in[6];
    const float* bv  = (const float*)d_in[7];
    const float* lng = (const float*)d_in[14];
    const float* lnb = (const float*)d_in[15];
    const float* W1  = (const float*)d_in[16];
    const float* b1  = (const float*)d_in[17];
    const float* W2  = (const float*)d_in[18];
    const float* b2  = (const float*)d_in[19];

    uint32_t *pxh, *pWqkv, *pW1t, *pW2t, *phnh, *pacth, *pqkvh;
    float *pbqkv, *pattn, *phn;
    cudaGetSymbolAddress((void**)&pxh,    g_xh);
    cudaGetSymbolAddress((void**)&pWqkv,  g_Wqkv);
    cudaGetSymbolAddress((void**)&pW1t,   g_W1t);
    cudaGetSymbolAddress((void**)&pW2t,   g_W2t);
    cudaGetSymbolAddress((void**)&pbqkv,  g_bqkv);
    cudaGetSymbolAddress((void**)&pqkvh,  g_qkvh);
    cudaGetSymbolAddress((void**)&pattn,  g_attn);
    cudaGetSymbolAddress((void**)&phn,    g_hn);
    cudaGetSymbolAddress((void**)&phnh,   g_hnh);
    cudaGetSymbolAddress((void**)&pacth,  g_acth);

    cudaFuncSetAttribute(hgemm2<0>, cudaFuncAttributeMaxDynamicSharedMemorySize, GSMEM);
    cudaFuncSetAttribute(hgemm2<1>, cudaFuncAttributeMaxDynamicSharedMemorySize, GSMEM);
    cudaFuncSetAttribute(hgemm2<2>, cudaFuncAttributeMaxDynamicSharedMemorySize, GSMEM);
    cudaFuncSetAttribute(attn_mma,  cudaFuncAttributeMaxDynamicSharedMemorySize, ASMEM);

    dim3 blk(256);
    const int PGRID = 296;   // 2 CTAs/SM x 148 SMs

    // 1: x->fp16   2: QKV weight transpose (+bias)
    prep_x<<<(int)(((size_t)MPAD * DMODEL / 2 + 255) / 256), blk>>>(x, pxh);
    prep_wqkv_t<<<dim3(8, 16, 3), blk>>>(Wq, Wk, Wv, bq, bk, bv, pWqkv, pbqkv);

    // 3: fused QKV GEMM (persistent, 296 CTAs over 768 tiles)
    hgemm2<0><<<PGRID, blk, GSMEM>>>(
        pxh, pWqkv, pbqkv, nullptr, nullptr, pqkvh, MPAD, QKVN, DMODEL);

    // 4: attention
    attn_mma<<<dim3(SEQ / 64, NH, BATCH), dim3(128), ASMEM>>>(pqkvh, pattn);

    // 5: W1 + W2 transposes (one launch)   6: residual + LN
    prep_w12<<<1024, blk>>>(W1, W2, pW1t, pW2t);
    ln_kernel<<<MROWS, blk>>>(x, pattn, lng, lnb, phn, phnh);

    // 7: FFN up + gelu (persistent, 296 over 1024 tiles)
    hgemm2<1><<<PGRID, blk, GSMEM>>>(
        phnh, pW1t, b1, nullptr, nullptr, pacth, MROWS, DFF, DMODEL);

    // 8: FFN down + bias + residual -> out (256 tiles <= 296: one tile each)
    hgemm2<2><<<256, blk, GSMEM>>>(
        pacth, pW2t, b2, phn, (float*)d_out, nullptr, MROWS, DMODEL, DFF);
}

// round 17
// speedup vs baseline: 1.1253x; 1.0562x over previous
#include <cuda_runtime.h>
#include <cuda_fp16.h>
#include <math.h>
#include <stdint.h>

#define BATCH   2
#define S0      4095
#define SEQ     4096
#define DMODEL  512
#define NH      8
#define DH      64
#define DFF     2048
#define MROWS   (BATCH * S0)    // 8190
#define MPAD    (BATCH * SEQ)   // 8192
#define QKVN    1536
#define QKVW    768             // words per qkv row

// ---------------- scratch ----------------
__device__ __align__(16) uint32_t g_xh[(size_t)MPAD * DMODEL / 2];
__device__ __align__(16) uint32_t g_Wqkv[(size_t)QKVN * DMODEL / 2];
__device__ __align__(16) uint32_t g_W1t[(size_t)DFF * DMODEL / 2];
__device__ __align__(16) uint32_t g_W2t[(size_t)DMODEL * DFF / 2];
__device__ __align__(16) float    g_bqkv[QKVN];
__device__ __align__(16) uint32_t g_qkvh[(size_t)MPAD * QKVW];   // packed fp16
__device__ __align__(16) float    g_attn[(size_t)MPAD * DMODEL];
__device__ __align__(16) float    g_hn[(size_t)MROWS * DMODEL];
__device__ __align__(16) uint32_t g_hnh[(size_t)MROWS * DMODEL / 2];
__device__ __align__(16) uint32_t g_acth[(size_t)MROWS * DFF / 2];

__device__ __forceinline__ uint32_t smem_u32(const void* p) {
    uint32_t a;
    asm("{ .reg .u64 t; cvta.to.shared.u64 t, %1; cvt.u32.u64 %0, t; }"
        : "=r"(a) : "l"(p));
    return a;
}
__device__ __forceinline__ uint32_t f2h2(float a, float b) {
    __half2 h = __floats2half2_rn(a, b);
    return *(uint32_t*)&h;
}
__device__ __forceinline__ float2 h22f2(uint32_t w) {
    __half2 h = *(__half2*)&w;
    return __half22float2(h);
}
__device__ __forceinline__ float gelu_exact(float v) {
    return 0.5f * v * (1.0f + erff(v * 0.70710678118654752440f));
}
__device__ __forceinline__ void mma_f16(float* c, const uint32_t* a,
                                        const uint32_t* b) {
    asm volatile(
        "mma.sync.aligned.m16n8k16.row.col.f32.f16.f16.f32 "
        "{%0,%1,%2,%3}, {%4,%5,%6,%7}, {%8,%9}, {%0,%1,%2,%3};"
        : "+f"(c[0]), "+f"(c[1]), "+f"(c[2]), "+f"(c[3])
        : "r"(a[0]), "r"(a[1]), "r"(a[2]), "r"(a[3]), "r"(b[0]), "r"(b[1]));
}
#define LDSM4(r0, r1, r2, r3, addr) \
    asm volatile("ldmatrix.sync.aligned.m8n8.x4.shared.b16 {%0,%1,%2,%3}, [%4];" \
        : "=r"(r0), "=r"(r1), "=r"(r2), "=r"(r3) : "r"(addr))
#define LDSM4T(r0, r1, r2, r3, addr) \
    asm volatile("ldmatrix.sync.aligned.m8n8.x4.trans.shared.b16 {%0,%1,%2,%3}, [%4];" \
        : "=r"(r0), "=r"(r1), "=r"(r2), "=r"(r3) : "r"(addr))

__device__ __forceinline__ void cpa16(uint32_t dst, const void* src, bool v) {
    int sz = v ? 16 : 0;
    asm volatile("cp.async.cg.shared.global [%0], [%1], 16, %2;"
        :: "r"(dst), "l"(src), "r"(sz) : "memory");
}

// ---------------------------------------------------------------------------
// Persistent fp16 GEMM (proven): block 128x128, warp 64x32, BK=32, 4-stage.
// B-frag pairs {r0,r1}/{r2,r3} per GEMM addressing (bit3->k, bit4->row+8).
// ---------------------------------------------------------------------------
#define STGW 5120
#define GSTAGES 4
#define GSMEM (GSTAGES * STGW * 4)

template<int MODE>
__global__ __launch_bounds__(256, 2)
void hgemm2(const uint32_t* __restrict__ A, const uint32_t* __restrict__ B,
            const float* __restrict__ bias, const float* __restrict__ res,
            float* __restrict__ outf, uint32_t* __restrict__ outh,
            int M, int N, int K)
{
    extern __shared__ __align__(16) uint32_t S[];
    const uint32_t sm0 = smem_u32(S);
    const int tid  = threadIdx.x;
    const int lane = tid & 31;
    const int wid  = tid >> 5;
    const int wm   = wid & 1;
    const int wn   = wid >> 1;
    const int K2   = K >> 1;
    const int NT   = K >> 5;
    const int nbn  = N >> 7;
    const int nTiles = ((M + 127) >> 7) * nbn;

    const int aRow = wm * 64 + (lane & 15);
    const int aW   = (lane >> 4) << 2;
    const int bRow = wn * 32 + (lane & 7) + ((lane >> 4) << 3);
    const int bW   = ((lane >> 3) & 1) << 2;

    for (int tix = blockIdx.x; tix < nTiles; tix += gridDim.x) {
        const int bm = tix / nbn;
        const int bn = tix - bm * nbn;

        auto load_stage = [&](int kt, int st) {
            const uint32_t base = sm0 + st * (STGW * 4);
#pragma unroll
            for (int i = 0; i < 4; i++) {
                int c = i * 256 + tid;
                bool isA = (c < 512);
                int idx  = isA ? c : c - 512;
                int row  = idx >> 2, w = idx & 3;
                int grow = (isA ? bm : bn) * 128 + row;
                bool valid = (!isA) || (grow < M);
                const uint32_t* src = (isA ? A : B)
                    + (size_t)(valid ? grow : 0) * K2 + kt * 16 + w * 4;
                uint32_t dst = base + ((isA ? 0 : 2560) + row * 20 + w * 4) * 4;
                cpa16(dst, src, valid);
            }
            asm volatile("cp.async.commit_group;" ::: "memory");
        };

        float acc[4][4][4];
#pragma unroll
        for (int i = 0; i < 4; i++)
#pragma unroll
            for (int j = 0; j < 4; j++)
#pragma unroll
                for (int q = 0; q < 4; q++) acc[i][j][q] = 0.0f;

        load_stage(0, 0);
        load_stage(1, 1);
        load_stage(2, 2);

        for (int kt = 0; kt < NT; kt++) {
            if (kt + 2 < NT)      asm volatile("cp.async.wait_group 2;" ::: "memory");
            else if (kt + 1 < NT) asm volatile("cp.async.wait_group 1;" ::: "memory");
            else                  asm volatile("cp.async.wait_group 0;" ::: "memory");
            __syncthreads();
            if (kt + 3 < NT) load_stage(kt + 3, (kt + 3) % GSTAGES);

            const uint32_t sA = sm0 + (kt % GSTAGES) * (STGW * 4);
            const uint32_t sB = sA + 2560 * 4;
#pragma unroll
            for (int kh = 0; kh < 2; kh++) {
                uint32_t a[4][4], b[4][2];
#pragma unroll
                for (int mf = 0; mf < 4; mf++) {
                    uint32_t ad = sA + (((aRow + mf * 16) * 20) + aW + kh * 8) * 4;
                    LDSM4(a[mf][0], a[mf][1], a[mf][2], a[mf][3], ad);
                }
#pragma unroll
                for (int bp = 0; bp < 2; bp++) {
                    uint32_t ad = sB + (((bRow + bp * 16) * 20) + bW + kh * 8) * 4;
                    LDSM4(b[2 * bp][0], b[2 * bp][1],
                          b[2 * bp + 1][0], b[2 * bp + 1][1], ad);
                }
#pragma unroll
                for (int mf = 0; mf < 4; mf++)
#pragma unroll
                    for (int nf = 0; nf < 4; nf++)
                        mma_f16(acc[mf][nf], a[mf], b[nf]);
            }
        }

#pragma unroll
        for (int mf = 0; mf < 4; mf++) {
#pragma unroll
            for (int nf = 0; nf < 4; nf++) {
                const int r0  = bm * 128 + wm * 64 + mf * 16 + (lane >> 2);
                const int col = bn * 128 + wn * 32 + nf * 8 + (lane & 3) * 2;
                const float b0 = bias[col], b1 = bias[col + 1];
#pragma unroll
                for (int half = 0; half < 2; half++) {
                    const int r = r0 + half * 8;
                    if (r >= M) continue;
                    float v0 = acc[mf][nf][half * 2 + 0] + b0;
                    float v1 = acc[mf][nf][half * 2 + 1] + b1;
                    if (MODE == 0) {
                        outh[(size_t)r * (N >> 1) + (col >> 1)] = f2h2(v0, v1);
                    } else if (MODE == 1) {
                        outh[(size_t)r * (N >> 1) + (col >> 1)] =
                            f2h2(gelu_exact(v0), gelu_exact(v1));
                    } else {
                        const float* rr = res + (size_t)r * N + col;
                        *(float2*)&outf[(size_t)r * N + col] =
                            make_float2(v0 + rr[0], v1 + rr[1]);
                    }
                }
            }
        }
    }
}

// ---------------------------------------------------------------------------
// prep kernels
// ---------------------------------------------------------------------------
__global__ void prep_x(const float* __restrict__ x, uint32_t* __restrict__ o)
{
    size_t idx = (size_t)blockIdx.x * blockDim.x + threadIdx.x;
    if (idx >= (size_t)MPAD * DMODEL / 2) return;
    int r = (int)(idx >> 8), w = (int)(idx & 255);
    int s = r & (SEQ - 1), b = r >> 12;
    float v0 = 0.f, v1 = 0.f;
    if (s < S0) {
        const float* p = x + ((size_t)b * S0 + s) * DMODEL + 2 * w;
        v0 = p[0]; v1 = p[1];
    }
    o[idx] = f2h2(v0, v1);
}

__device__ __forceinline__ void wt_tile(const float* __restrict__ W,
                                        uint32_t* __restrict__ o,
                                        int N, int dstStride, int dstRowOff,
                                        float scale, int k0, int n0)
{
    __shared__ float ts[64][33];
    const int tid = threadIdx.x;
#pragma unroll
    for (int i = 0; i < 8; i++) {
        int t = i * 256 + tid;
        int kr = t >> 5, nc = t & 31;
        ts[kr][nc] = W[(size_t)(k0 + kr) * N + n0 + nc];
    }
    __syncthreads();
#pragma unroll
    for (int i = 0; i < 4; i++) {
        int t = i * 256 + tid;
        int n = t >> 5, w = t & 31;
        o[(size_t)(dstRowOff + n0 + n) * dstStride + (k0 >> 1) + w] =
            f2h2(ts[2 * w][n] * scale, ts[2 * w + 1][n] * scale);
    }
}

__global__ __launch_bounds__(256)
void prep_wqkv_t(const float* __restrict__ Wq, const float* __restrict__ Wk,
                 const float* __restrict__ Wv,
                 const float* __restrict__ bq, const float* __restrict__ bk,
                 const float* __restrict__ bv,
                 uint32_t* __restrict__ o, float* __restrict__ obias)
{
    const int z = blockIdx.z;
    const float* W = (z == 0) ? Wq : (z == 1) ? Wk : Wv;
    float sc = (z == 0) ? 0.125f : 1.0f;
    wt_tile(W, o, DMODEL, 256, z * 512, sc, blockIdx.x * 64, blockIdx.y * 32);
    if (z == 0 && blockIdx.x == 0 && blockIdx.y == 0) {
#pragma unroll
        for (int i = 0; i < 6; i++) {
            int n = i * 256 + threadIdx.x;
            obias[n] = (n < 512) ? bq[n] * 0.125f
                     : (n < 1024) ? bk[n - 512] : bv[n - 1024];
        }
    }
}

__global__ __launch_bounds__(256)
void prep_w12(const float* __restrict__ W1, const float* __restrict__ W2,
              uint32_t* __restrict__ o1, uint32_t* __restrict__ o2)
{
    int bid = blockIdx.x;
    if (bid < 512) {
        int kIdx = bid >> 6, nIdx = bid & 63;
        wt_tile(W1, o1, DFF, 256, 0, 1.0f, kIdx * 64, nIdx * 32);
    } else {
        int b2 = bid - 512;
        int kIdx = b2 >> 4, nIdx = b2 & 15;
        wt_tile(W2, o2, DMODEL, 1024, 0, 1.0f, kIdx * 64, nIdx * 32);
    }
}

// ---------------------------------------------------------------------------
// Tensor-core sliding-window attention, v2.
// V staged like K ([320][72], coalesced uint4, no transpose). PV B-frags via
// ldmatrix.x4.trans: with row=key (l15), col bit via lane>>4 (lh8), matrices
// are (keyblk x dblk)^T, so pairs are {r0,r1} (d p*16..+7), {r2,r3} (d+8..15).
// Masking uses unsigned compares. 2 CTAs/SM.
// ---------------------------------------------------------------------------
#define AQ0 0
#define AK0 (64 * 72)                     // 4608
#define AV0 (AK0 + 320 * 72)              // 27648
#define ASMEMH (AV0 + 320 * 72)           // 50688 halves
#define ASMEM (ASMEMH * 2)                // 101376 bytes

__global__ __launch_bounds__(128, 2)
void attn_mma(const uint32_t* __restrict__ qkvh, float* __restrict__ out)
{
    extern __shared__ __align__(16) unsigned short SH[];
    const uint32_t sb = smem_u32(SH);
    const int tid  = threadIdx.x;
    const int lane = tid & 31;
    const int w    = tid >> 5;
    const int h    = blockIdx.y;
    const int b    = blockIdx.z;
    const int t0   = blockIdx.x * 64;
    const size_t rowbase = (size_t)b * SEQ;

#pragma unroll
    for (int i = 0; i < 4; i++) {
        int c = i * 128 + tid;
        int row = c >> 3, c16 = c & 7;
        const uint32_t* src = qkvh + (rowbase + t0 + row) * QKVW + h * 32 + c16 * 4;
        *(uint4*)&SH[AQ0 + row * 72 + c16 * 8] = *(const uint4*)src;
    }
#pragma unroll
    for (int i = 0; i < 20; i++) {
        int c = i * 128 + tid;
        int row = c >> 3, c16 = c & 7;
        int key = t0 - 128 + row;
        key = key < 0 ? 0 : (key > SEQ - 1 ? SEQ - 1 : key);
        const uint32_t* src = qkvh + (rowbase + key) * QKVW + 256 + h * 32 + c16 * 4;
        *(uint4*)&SH[AK0 + row * 72 + c16 * 8] = *(const uint4*)src;
    }
#pragma unroll
    for (int i = 0; i < 20; i++) {
        int c = i * 128 + tid;
        int row = c >> 3, c16 = c & 7;
        int key = t0 - 128 + row;
        key = key < 0 ? 0 : (key > SEQ - 1 ? SEQ - 1 : key);
        const uint32_t* src = qkvh + (rowbase + key) * QKVW + 512 + h * 32 + c16 * 4;
        *(uint4*)&SH[AV0 + row * 72 + c16 * 8] = *(const uint4*)src;
    }
    __syncthreads();

    const int l15 = lane & 15;
    const int lh8 = (lane >> 4) << 3;
    const int kl0 = (lane & 3) << 1;
    const int r   = 16 * w + (lane >> 2);

    uint32_t aq[4][4];
#pragma unroll
    for (int j = 0; j < 4; j++) {
        uint32_t ad = sb + ((16 * w + l15) * 72 + 16 * j + lh8) * 2;
        LDSM4(aq[j][0], aq[j][1], aq[j][2], aq[j][3], ad);
    }

    float od[8][4];
#pragma unroll
    for (int nf = 0; nf < 8; nf++)
#pragma unroll
        for (int q = 0; q < 4; q++) od[nf][q] = 0.0f;
    float m0 = -1e30f, m1 = -1e30f, l0 = 0.f, l1 = 0.f;

    for (int c = 0; c < 5; c++) {
        const int ks = t0 - 128 + 64 * c;
        if (ks + 63 < 0 || ks > S0 - 1) continue;

        float sc[8][4];
#pragma unroll
        for (int nf = 0; nf < 8; nf++)
#pragma unroll
            for (int q = 0; q < 4; q++) sc[nf][q] = 0.0f;

        // S = Q @ K^T  (K addressing bit0-3->row, bit4->k-off: pairs {r0,r2})
#pragma unroll
        for (int j = 0; j < 4; j++)
#pragma unroll
            for (int p = 0; p < 4; p++) {
                uint32_t r0, r1, r2, r3;
                uint32_t ad = sb + (AK0 + (c * 64 + 16 * p + l15) * 72
                                    + 16 * j + lh8) * 2;
                LDSM4(r0, r1, r2, r3, ad);
                uint32_t b0[2] = {r0, r2}, b1[2] = {r1, r3};
                mma_f16(sc[2 * p],     aq[j], b0);
                mma_f16(sc[2 * p + 1], aq[j], b1);
            }

        // mask (unsigned-compare trick) + row max
        float mx0 = -1e30f, mx1 = -1e30f;
#pragma unroll
        for (int nf = 0; nf < 8; nf++) {
            int kl = 8 * nf + kl0;
            int u  = 64 * c + kl - r;
            int sg = ks + kl;
            bool v0 = ((unsigned)sg < (unsigned)S0)       && ((unsigned)u <= 256u);
            bool v1 = ((unsigned)(sg + 1) < (unsigned)S0) && ((unsigned)(u + 1) <= 256u);
            bool v2 = ((unsigned)sg < (unsigned)S0)       && ((unsigned)(u - 8) <= 256u);
            bool v3 = ((unsigned)(sg + 1) < (unsigned)S0) && ((unsigned)(u - 7) <= 256u);
            sc[nf][0] = v0 ? sc[nf][0] : -1e30f;
            sc[nf][1] = v1 ? sc[nf][1] : -1e30f;
            sc[nf][2] = v2 ? sc[nf][2] : -1e30f;
            sc[nf][3] = v3 ? sc[nf][3] : -1e30f;
            mx0 = fmaxf(mx0, fmaxf(sc[nf][0], sc[nf][1]));
            mx1 = fmaxf(mx1, fmaxf(sc[nf][2], sc[nf][3]));
        }
        mx0 = fmaxf(mx0, __shfl_xor_sync(0xffffffffu, mx0, 1));
        mx0 = fmaxf(mx0, __shfl_xor_sync(0xffffffffu, mx0, 2));
        mx1 = fmaxf(mx1, __shfl_xor_sync(0xffffffffu, mx1, 1));
        mx1 = fmaxf(mx1, __shfl_xor_sync(0xffffffffu, mx1, 2));

        float mn0 = fmaxf(m0, mx0), mn1 = fmaxf(m1, mx1);
        float s0 = __expf(m0 - mn0), s1 = __expf(m1 - mn1);
        float ls0 = 0.f, ls1 = 0.f;
        uint32_t pa[4][4];
#pragma unroll
        for (int nf = 0; nf < 8; nf++) {
            float e0 = __expf(sc[nf][0] - mn0);
            float e1 = __expf(sc[nf][1] - mn0);
            float e2 = __expf(sc[nf][2] - mn1);
            float e3 = __expf(sc[nf][3] - mn1);
            ls0 += e0 + e1; ls1 += e2 + e3;
            int j = nf >> 1, q = nf & 1;
            pa[j][2 * q]     = f2h2(e0, e1);
            pa[j][2 * q + 1] = f2h2(e2, e3);
        }
        ls0 += __shfl_xor_sync(0xffffffffu, ls0, 1);
        ls0 += __shfl_xor_sync(0xffffffffu, ls0, 2);
        ls1 += __shfl_xor_sync(0xffffffffu, ls1, 1);
        ls1 += __shfl_xor_sync(0xffffffffu, ls1, 2);
        l0 = l0 * s0 + ls0;
        l1 = l1 * s1 + ls1;
        m0 = mn0; m1 = mn1;
#pragma unroll
        for (int nf = 0; nf < 8; nf++) {
            od[nf][0] *= s0; od[nf][1] *= s0;
            od[nf][2] *= s1; od[nf][3] *= s1;
        }

        // O += P @ V  (trans loads: pairs {r0,r1} d..+7, {r2,r3} d+8..15)
#pragma unroll
        for (int j = 0; j < 4; j++)
#pragma unroll
            for (int p = 0; p < 4; p++) {
                uint32_t r0, r1, r2, r3;
                uint32_t ad = sb + (AV0 + (c * 64 + 16 * j + l15) * 72
                                    + 16 * p + lh8) * 2;
                LDSM4T(r0, r1, r2, r3, ad);
                uint32_t b0[2] = {r0, r1}, b1[2] = {r2, r3};
                mma_f16(od[2 * p],     pa[j], b0);
                mma_f16(od[2 * p + 1], pa[j], b1);
            }
    }

    {   // global key (row SEQ-1)
        const uint32_t* kg = qkvh + (rowbase + SEQ - 1) * QKVW + 256 + h * 32
                           + (lane & 3) * 8;
        const uint32_t* q0 = (const uint32_t*)(SH + (size_t)(AQ0 + r * 72))
                           + (lane & 3) * 8;
        const uint32_t* q1 = (const uint32_t*)(SH + (size_t)(AQ0 + (r + 8) * 72))
                           + (lane & 3) * 8;
        float gs0 = 0.f, gs1 = 0.f;
#pragma unroll
        for (int i = 0; i < 8; i++) {
            float2 fk = h22f2(kg[i]);
            float2 f0 = h22f2(q0[i]);
            float2 f1 = h22f2(q1[i]);
            gs0 += f0.x * fk.x + f0.y * fk.y;
            gs1 += f1.x * fk.x + f1.y * fk.y;
        }
        gs0 += __shfl_xor_sync(0xffffffffu, gs0, 1);
        gs0 += __shfl_xor_sync(0xffffffffu, gs0, 2);
        gs1 += __shfl_xor_sync(0xffffffffu, gs1, 1);
        gs1 += __shfl_xor_sync(0xffffffffu, gs1, 2);

        float mn0 = fmaxf(m0, gs0), mn1 = fmaxf(m1, gs1);
        float s0 = __expf(m0 - mn0), s1 = __expf(m1 - mn1);
        float pg0 = __expf(gs0 - mn0), pg1 = __expf(gs1 - mn1);
        l0 = l0 * s0 + pg0;
        l1 = l1 * s1 + pg1;
        const uint32_t* vg = qkvh + (rowbase + SEQ - 1) * QKVW + 512 + h * 32
                           + (lane & 3);
#pragma unroll
        for (int nf = 0; nf < 8; nf++) {
            float2 fv = h22f2(vg[nf * 4]);
            od[nf][0] = od[nf][0] * s0 + pg0 * fv.x;
            od[nf][1] = od[nf][1] * s0 + pg0 * fv.y;
            od[nf][2] = od[nf][2] * s1 + pg1 * fv.x;
            od[nf][3] = od[nf][3] * s1 + pg1 * fv.y;
        }
    }

    const float inv0 = 1.0f / l0, inv1 = 1.0f / l1;
    const int t = t0 + r;
    float* o0 = out + ((size_t)b * SEQ + t) * DMODEL + h * DH + kl0;
    float* o1 = o0 + 8 * (size_t)DMODEL;
#pragma unroll
    for (int nf = 0; nf < 8; nf++) {
        *(float2*)(o0 + nf * 8) = make_float2(od[nf][0] * inv0, od[nf][1] * inv0);
        *(float2*)(o1 + nf * 8) = make_float2(od[nf][2] * inv1, od[nf][3] * inv1);
    }
}

// ---------------------------------------------------------------------------
// Residual + LayerNorm -> hn fp32 + packed fp16
// ---------------------------------------------------------------------------
__global__ __launch_bounds__(256)
void ln_kernel(const float* __restrict__ x, const float* __restrict__ attn,
               const float* __restrict__ gamma, const float* __restrict__ beta,
               float* __restrict__ hn, uint32_t* __restrict__ hnh)
{
    const int r = blockIdx.x;
    const int b = r / S0;
    const int s = r - b * S0;
    const int tid = threadIdx.x;
    const int c = tid * 2;

    float2 xv = *(const float2*)(x + (size_t)r * DMODEL + c);
    float2 av = *(const float2*)(attn + ((size_t)b * SEQ + s) * DMODEL + c);
    float h0 = xv.x + av.x;
    float h1 = xv.y + av.y;
    float sum = h0 + h1;
    float sq  = h0 * h0 + h1 * h1;
#pragma unroll
    for (int off = 16; off; off >>= 1) {
        sum += __shfl_xor_sync(0xffffffffu, sum, off);
        sq  += __shfl_xor_sync(0xffffffffu, sq,  off);
    }
    __shared__ float rs[8], rq[8];
    int w = tid >> 5, lane = tid & 31;
    if (lane == 0) { rs[w] = sum; rq[w] = sq; }
    __syncthreads();
    float ts = 0.f, tq = 0.f;
#pragma unroll
    for (int i = 0; i < 8; i++) { ts += rs[i]; tq += rq[i]; }
    float mu   = ts * (1.0f / DMODEL);
    float var  = tq * (1.0f / DMODEL) - mu * mu;
    float rstd = rsqrtf(var + 1e-5f);
    float v0 = (h0 - mu) * rstd * gamma[c]     + beta[c];
    float v1 = (h1 - mu) * rstd * gamma[c + 1] + beta[c + 1];
    size_t base = (size_t)r * DMODEL;
    *(float2*)(hn + base + c) = make_float2(v0, v1);
    hnh[(base >> 1) + tid] = f2h2(v0, v1);
}

// ---------------------------------------------------------------------------
extern "C" void kernel_launch(void* const* d_in, const int* in_sizes, int n_in,
                              void* d_out, int out_size)
{
    const float* x   = (const float*)d_in[0];
    const float* Wq  = (const float*)d_in[2];
    const float* bq  = (const float*)d_in[3];
    const float* Wk  = (const float*)d_in[4];
    const float* bk  = (const float*)d_in[5];
    const float* Wv  = (const float*)d_in[6];
    const float* bv  = (const float*)d_in[7];
    const float* lng = (const float*)d_in[14];
    const float* lnb = (const float*)d_in[15];
    const float* W1  = (const float*)d_in[16];
    const float* b1  = (const float*)d_in[17];
    const float* W2  = (const float*)d_in[18];
    const float* b2  = (const float*)d_in[19];

    uint32_t *pxh, *pWqkv, *pW1t, *pW2t, *phnh, *pacth, *pqkvh;
    float *pbqkv, *pattn, *phn;
    cudaGetSymbolAddress((void**)&pxh,    g_xh);
    cudaGetSymbolAddress((void**)&pWqkv,  g_Wqkv);
    cudaGetSymbolAddress((void**)&pW1t,   g_W1t);
    cudaGetSymbolAddress((void**)&pW2t,   g_W2t);
    cudaGetSymbolAddress((void**)&pbqkv,  g_bqkv);
    cudaGetSymbolAddress((void**)&pqkvh,  g_qkvh);
    cudaGetSymbolAddress((void**)&pattn,  g_attn);
    cudaGetSymbolAddress((void**)&phn,    g_hn);
    cudaGetSymbolAddress((void**)&phnh,   g_hnh);
    cudaGetSymbolAddress((void**)&pacth,  g_acth);

    cudaFuncSetAttribute(hgemm2<0>, cudaFuncAttributeMaxDynamicSharedMemorySize, GSMEM);
    cudaFuncSetAttribute(hgemm2<1>, cudaFuncAttributeMaxDynamicSharedMemorySize, GSMEM);
    cudaFuncSetAttribute(hgemm2<2>, cudaFuncAttributeMaxDynamicSharedMemorySize, GSMEM);
    cudaFuncSetAttribute(attn_mma,  cudaFuncAttributeMaxDynamicSharedMemorySize, ASMEM);

    dim3 blk(256);
    const int PGRID = 296;

    prep_x<<<(int)(((size_t)MPAD * DMODEL / 2 + 255) / 256), blk>>>(x, pxh);
    prep_wqkv_t<<<dim3(8, 16, 3), blk>>>(Wq, Wk, Wv, bq, bk, bv, pWqkv, pbqkv);

    hgemm2<0><<<PGRID, blk, GSMEM>>>(
        pxh, pWqkv, pbqkv, nullptr, nullptr, pqkvh, MPAD, QKVN, DMODEL);

    attn_mma<<<dim3(SEQ / 64, NH, BATCH), dim3(128), ASMEM>>>(pqkvh, pattn);

    prep_w12<<<1024, blk>>>(W1, W2, pW1t, pW2t);
    ln_kernel<<<MROWS, blk>>>(x, pattn, lng, lnb, phn, phnh);

    hgemm2<1><<<PGRID, blk, GSMEM>>>(
        phnh, pW1t, b1, nullptr, nullptr, pacth, MROWS, DFF, DMODEL);

    hgemm2<2><<<256, blk, GSMEM>>>(
        pacth, pW2t, b2, phn, (float*)d_out, nullptr, MROWS, DMODEL, DFF);
}